// round 9
// baseline (speedup 1.0000x reference)
#include <cuda_runtime.h>
#include <cuda_bf16.h>
#include <cstdint>

#define B_SZ 512
#define HID 256
#define TLEN 23
#define FLATN 5184

typedef unsigned long long ull;

// ---------------- scratch ----------------
__device__ float g_buf1[B_SZ * 12 * 36 * 3 * 16];   // conv1 pooled NDHWC
__device__ float g_p2[B_SZ * 12 * 36 * 3 * 32];     // conv2 RAW pre-pool NDHWC
__device__ float g_p3[B_SZ * 6 * 18 * 3 * 64];      // conv3 RAW pre-pool NDHWC
__device__ float g_buf3[B_SZ * 3 * 9 * 3 * 64];     // conv3 pooled NDHWC == flat
__device__ float g_h[B_SZ * HID];
__device__ float g_h2[B_SZ * HID];
__device__ float g_ih[B_SZ * HID];
__device__ float g_t1[B_SZ * HID];

// conv1 weights transposed + f32x2-dup: [(ic*27 + tap)*16 + oc]
__device__ ull g_wc1[162 * 16];

// tf32 weight fragments, B-fragment order: [((t*KC+kc)*N8TOT + n8)*32 + lane]
__device__ float2 g_f2[27 * 2 * 4 * 32];     // conv2: KC=2, N8TOT=4
__device__ float2 g_f3[27 * 4 * 8 * 32];     // conv3: KC=4, N8TOT=8

// matmul weights packed-transposed [k4][j]
__device__ ulonglong2 g_wt[3 * 64 * 256];
__device__ ulonglong2 g_wAq[16 * 256];
__device__ ulonglong2 g_wBq[16 * 256];
__device__ ulonglong2 g_wCq[64 * 256];
__device__ ulonglong2 g_wl1t[1296 * 256];

// ---------------- helpers ----------------
__device__ __forceinline__ void fma2(ull& acc, ull a, ull b) {
    asm("fma.rn.f32x2 %0, %1, %2, %0;" : "+l"(acc) : "l"(a), "l"(b));
}
__device__ __forceinline__ ull pk2(float lo, float hi) {
    ull r; asm("mov.b64 %0, {%1,%2};" : "=l"(r) : "f"(lo), "f"(hi)); return r;
}
__device__ __forceinline__ float2 upk(ull v) {
    float lo, hi; asm("mov.b64 {%0,%1}, %2;" : "=f"(lo), "=f"(hi) : "l"(v));
    return make_float2(lo, hi);
}
__device__ __forceinline__ uint32_t ctf(float v) {
    uint32_t r; asm("cvt.rna.tf32.f32 %0, %1;" : "=r"(r) : "f"(v)); return r;
}
__device__ __forceinline__ void mma8(float c[4], uint32_t a0, uint32_t a1,
                                     uint32_t a2, uint32_t a3,
                                     uint32_t b0, uint32_t b1) {
    asm("mma.sync.aligned.m16n8k8.row.col.f32.tf32.tf32.f32 "
        "{%0,%1,%2,%3}, {%4,%5,%6,%7}, {%8,%9}, {%0,%1,%2,%3};"
        : "+f"(c[0]), "+f"(c[1]), "+f"(c[2]), "+f"(c[3])
        : "r"(a0), "r"(a1), "r"(a2), "r"(a3), "r"(b0), "r"(b1));
}

// ---------------- weight packers ----------------
__global__ __launch_bounds__(256) void pack_convw_kernel(const float* __restrict__ w1)
{
    const int idx = blockIdx.x * 256 + threadIdx.x;
    if (idx >= 2592) return;
    const int oc = idx % 16, k = idx / 16;
    const float v = w1[(size_t)oc * 162 + k];
    g_wc1[idx] = pk2(v, v);
}

// tf32 B-fragment layout: B[k][n], k = kc*8 + (lane&3) (+4), n = n8*8 + (lane>>2)
__global__ __launch_bounds__(256) void pack_frag_kernel(
    const float* __restrict__ w2, const float* __restrict__ w3)
{
    const int idx = blockIdx.x * 256 + threadIdx.x;
    if (idx < 6912) {                       // conv2
        const int lane = idx & 31; int r = idx >> 5;
        const int n8 = r % 4; r /= 4;
        const int kc = r % 2; const int t = r / 2;
        const int oc = n8 * 8 + (lane >> 2), c = lane & 3;
        const int ic0 = kc * 8 + c, ic1 = ic0 + 4;
        const float v0 = w2[((size_t)oc * 16 + ic0) * 27 + t];
        const float v1 = w2[((size_t)oc * 16 + ic1) * 27 + t];
        g_f2[idx] = make_float2(__uint_as_float(ctf(v0)), __uint_as_float(ctf(v1)));
    } else if (idx < 6912 + 27648) {        // conv3
        const int j = idx - 6912;
        const int lane = j & 31; int r = j >> 5;
        const int n8 = r % 8; r /= 8;
        const int kc = r % 4; const int t = r / 4;
        const int oc = n8 * 8 + (lane >> 2), c = lane & 3;
        const int ic0 = kc * 8 + c, ic1 = ic0 + 4;
        const float v0 = w3[((size_t)oc * 32 + ic0) * 27 + t];
        const float v1 = w3[((size_t)oc * 32 + ic1) * 27 + t];
        g_f3[j] = make_float2(__uint_as_float(ctf(v0)), __uint_as_float(ctf(v1)));
    }
}

__global__ __launch_bounds__(256) void pack_weights_kernel(
    const float* __restrict__ whh1, const float* __restrict__ wih2,
    const float* __restrict__ whh2, const float* __restrict__ w_init_h,
    const float* __restrict__ wih1, const float* __restrict__ w_init_h2,
    const float* __restrict__ w_lin1)
{
    const int idx = blockIdx.x * 256 + threadIdx.x;   // < 405504
    const float* src; ulonglong2* dst; int K; int local;
    if (idx < 49152)      { int m = idx / 16384; local = idx % 16384;
                            src = (m == 0) ? whh1 : ((m == 1) ? wih2 : whh2);
                            dst = g_wt + m * 16384; K = 256; }
    else if (idx < 53248) { local = idx - 49152; src = w_init_h;  dst = g_wAq;  K = 64; }
    else if (idx < 57344) { local = idx - 53248; src = wih1;      dst = g_wBq;  K = 64; }
    else if (idx < 73728) { local = idx - 57344; src = w_init_h2; dst = g_wCq;  K = 256; }
    else                  { local = idx - 73728; src = w_lin1;    dst = g_wl1t; K = 5184; }
    const int j = local % 256;
    const int k4 = local / 256;
    const float4 v = *(const float4*)&src[(size_t)j * K + k4 * 4];
    ulonglong2 o; o.x = pk2(v.x, v.y); o.y = pk2(v.z, v.w);
    dst[local] = o;
}

// ---------------------------------------------------------------------------
// conv1: SIMT f32x2 (exact fp32; protects rel_err margin)
// ---------------------------------------------------------------------------
template <int IC, int OC, int DSLAB, int H, int WCH, bool SAFE>
__device__ __forceinline__ void conv_acc(
    const float* __restrict__ xs, const ull* __restrict__ ws,
    int oc, int icbase, int dsl, int ph, bool dlo, bool dhi, ull acc[3][2][3])
{
#pragma unroll 1
    for (int icl = 0; icl < WCH; icl++) {
        const float* xb = xs + icbase + icl;
        const ull* wb = ws + icl * 27 * OC + oc;
#pragma unroll
        for (int hxr = 0; hxr < 4; hxr++) {
            const int hx = 2 * ph - 1 + hxr;
            const bool hok = SAFE || ((unsigned)hx < (unsigned)H);
            ull xq[3][7];
#pragma unroll
            for (int c = 0; c < 3; c++) {
                float xr[8];
#pragma unroll
                for (int i = 0; i < 8; i++) {
                    bool ok = hok;
                    if (i == 0) ok = ok && !dlo;
                    if (i == 7) ok = ok && !dhi;
                    xr[i] = ok ? xb[(((dsl + i) * H + hx) * 3 + c) * IC] : 0.f;
                }
#pragma unroll
                for (int i = 0; i < 7; i++) xq[c][i] = pk2(xr[i], xr[i + 1]);
            }
#pragma unroll
            for (int ch = 0; ch < 2; ch++) {
                const int kh = hxr - ch;
                if (kh < 0 || kh > 2) continue;
#pragma unroll
                for (int kd = 0; kd < 3; kd++) {
                    const ull* wp = wb + (kd * 9 + kh * 3) * OC;
                    const ull W0 = wp[0];
                    const ull W1 = wp[OC];
                    const ull W2 = wp[2 * OC];
#pragma unroll
                    for (int p = 0; p < 3; p++) {
                        const int xi = 2 * p + kd;
                        fma2(acc[p][ch][0], W1, xq[0][xi]);
                        fma2(acc[p][ch][0], W2, xq[1][xi]);
                        fma2(acc[p][ch][1], W0, xq[0][xi]);
                        fma2(acc[p][ch][1], W1, xq[1][xi]);
                        fma2(acc[p][ch][1], W2, xq[2][xi]);
                        fma2(acc[p][ch][2], W0, xq[1][xi]);
                        fma2(acc[p][ch][2], W1, xq[2][xi]);
                    }
                }
            }
        }
    }
}

template <int IC, int OC, int D, int H, int WCH, int NDH>
__global__ __launch_bounds__(576, 1) void conv_k(
    const float* __restrict__ x, const ull* __restrict__ wT,
    const float* __restrict__ bias, float* __restrict__ out)
{
    constexpr int H2 = H / 2;
    constexpr int D2 = D / 2;
    constexpr int DSLAB = 6 * NDH + 1;
    constexpr int SLAB = DSLAB * H * 3 * IC;
    constexpr int WSZ = WCH * 27 * OC;
    extern __shared__ float sm[];
    float* xs = sm;
    ull* ws = (ull*)(sm + SLAB);

    const int b = blockIdx.x;
    const int half = blockIdx.y;
    const int dbase = half * (6 * NDH - 1);
    const int tid = threadIdx.x;
    const int oc = tid % OC;
    const int ph = tid / OC;

    {   // NCDHW -> transposed slab
        const float* xb = x + (size_t)b * IC * D * H * 3;
        for (int i = tid; i < SLAB; i += 576) {
            const int ic = i / (DSLAB * H * 3), s = i - ic * (DSLAB * H * 3);
            xs[s * IC + ic] = xb[ic * D * H * 3 + dbase * H * 3 + s];
        }
    }
    {
        const ulonglong2* wsrc = (const ulonglong2*)wT;
        ulonglong2* wdst = (ulonglong2*)ws;
        for (int i = tid; i < WSZ / 2; i += 576) wdst[i] = wsrc[i];
    }
    __syncthreads();

    const bool hsafe = (ph > 0) && (ph < H2 - 1);
    const float bv = __ldg(&bias[oc]);

#pragma unroll 1
    for (int pdb = 0; pdb < NDH; pdb++) {
        ull acc[3][2][3];
#pragma unroll
        for (int p = 0; p < 3; p++)
#pragma unroll
            for (int c = 0; c < 2; c++)
#pragma unroll
                for (int w = 0; w < 3; w++) acc[p][c][w] = 0ull;

        const bool dlo = (half == 0) && (pdb == 0);
        const bool dhi = (half == 1) && (pdb == NDH - 1);
        const int dsl = 6 * pdb - 1 + half;

        if (hsafe)
            conv_acc<IC, OC, DSLAB, H, WCH, true>(xs, ws, oc, 0, dsl, ph, dlo, dhi, acc);
        else
            conv_acc<IC, OC, DSLAB, H, WCH, false>(xs, ws, oc, 0, dsl, ph, dlo, dhi, acc);

#pragma unroll
        for (int p = 0; p < 3; p++) {
            const int pd = (half * NDH + pdb) * 3 + p;
#pragma unroll
            for (int pw = 0; pw < 3; pw++) {
                const float2 u0 = upk(acc[p][0][pw]);
                const float2 u1 = upk(acc[p][1][pw]);
                float m = fmaxf(fmaxf(u0.x, u0.y), fmaxf(u1.x, u1.y)) + bv;
                out[((((size_t)b * D2 + pd) * H2 + ph) * 3 + pw) * OC + oc] = fmaxf(m, 0.f);
            }
        }
    }
}

// ---------------------------------------------------------------------------
// conv2/conv3: tf32 mma.sync implicit GEMM, v2.
//  - slab stores tf32-converted values (cvt once per element at fill)
//  - B fragments staged in smem (no LDG in inner loop)
//  - block = (batch, d-group of DR, n-chunk of NT*16 channels)
// ---------------------------------------------------------------------------
template <int ICR, int D, int H, int DR, int KC, int NT, int N8TOT, bool POOLIN>
__global__ __launch_bounds__(256, 2) void conv_mma2(
    const float* __restrict__ x, const float* __restrict__ pbias,
    const float2* __restrict__ fragG, float* __restrict__ outRaw)
{
    constexpr int ICP = KC * 8;
    constexpr int Hp = H + 2, Wp = 5;
    constexpr int SLAB = (DR + 2) * Hp * Wp * ICP;
    constexpr int M = DR * H * 3;
    constexpr int MT = (M + 15) / 16;
    constexpr int N8B = 2 * NT;                 // n8 slots per block
    constexpr int FRAG = 27 * KC * N8B * 32;    // float2 count
    constexpr int OCTOT = N8TOT * 8;

    extern __shared__ __align__(16) char smraw[];
    float* xs = (float*)smraw;                  // SLAB floats (tf32 bits)
    float2* bf = (float2*)(smraw + SLAB * 4);   // FRAG float2

    const int b = blockIdx.x;
    const int d0 = blockIdx.y * DR;
    const int zn = blockIdx.z;                  // n-chunk
    const int tid = threadIdx.x;

    // ---- padded slab fill (tf32-converted) ----
    for (int i = tid; i < SLAB; i += 256) {
        const int ic = i % ICP; int r = i / ICP;
        const int wp = r % Wp; r /= Wp;
        const int hp = r % Hp; const int dp = r / Hp;
        const int d = d0 + dp - 1, h = hp - 1, w = wp - 1;
        float v = 0.f;
        if ((unsigned)d < (unsigned)D && (unsigned)h < (unsigned)H &&
            (unsigned)w < 3u && ic < ICR) {
            if (POOLIN) {
                const float* p = x + ((((size_t)b * 2 * D + 2 * d) * 2 * H + 2 * h) * 3 + w) * ICR + ic;
                const int sd = 2 * H * 3 * ICR, sh = 3 * ICR;
                const float m = fmaxf(fmaxf(p[0], p[sd]), fmaxf(p[sh], p[sd + sh]));
                v = fmaxf(m + __ldg(&pbias[ic]), 0.f);
            } else {
                v = x[((((size_t)b * D + d) * H + h) * 3 + w) * ICR + ic];
            }
        }
        xs[i] = __uint_as_float(ctf(v));
    }
    // ---- stage B fragments ----
    for (int i = tid; i < FRAG; i += 256) {
        const int lane = i & 31; int r = i >> 5;
        const int n8l = r % N8B; const int tk = r / N8B;
        bf[i] = __ldg(&fragG[((size_t)tk * N8TOT + zn * N8B + n8l) * 32 + lane]);
    }
    __syncthreads();

    const int warp = tid >> 5, lane = tid & 31;
    const int gid = lane >> 2, tig = lane & 3;
    const uint32_t* xsu = (const uint32_t*)xs;

#pragma unroll 1
    for (int item = warp; item < MT * NT; item += 8) {
        const int nt = item % NT, mt = item / NT;
        const int r0 = mt * 16 + gid, r1 = r0 + 8;
        const bool v0 = r0 < M, v1 = r1 < M;
        const int q0 = v0 ? r0 : M - 1, q1 = v1 ? r1 : M - 1;
        const int dl0 = q0 / (H * 3), t0r = q0 - dl0 * H * 3;
        const int h0 = t0r / 3, w0 = t0r - h0 * 3;
        const int dl1 = q1 / (H * 3), t1r = q1 - dl1 * H * 3;
        const int h1 = t1r / 3, w1 = t1r - h1 * 3;
        const int base0 = ((dl0 * Hp + h0) * Wp + w0) * ICP + tig;
        const int base1 = ((dl1 * Hp + h1) * Wp + w1) * ICP + tig;
        const float2* bfi = bf + (nt * 2) * 32 + lane;

        float acc0[4] = {0.f, 0.f, 0.f, 0.f};
        float acc1[4] = {0.f, 0.f, 0.f, 0.f};

#pragma unroll
        for (int t = 0; t < 27; t++) {
            const int kd = t / 9, kr = t - kd * 9, kh = kr / 3, kw = kr - kh * 3;
            const int toff = ((kd * Hp + kh) * Wp + kw) * ICP;
#pragma unroll
            for (int kc = 0; kc < KC; kc++) {
                const int ko = toff + kc * 8;
                const uint32_t a0 = xsu[base0 + ko];
                const uint32_t a1 = xsu[base1 + ko];
                const uint32_t a2 = xsu[base0 + ko + 4];
                const uint32_t a3 = xsu[base1 + ko + 4];
                const float2 bA = bfi[(t * KC + kc) * N8B * 32];
                const float2 bB = bfi[(t * KC + kc) * N8B * 32 + 32];
                mma8(acc0, a0, a1, a2, a3, __float_as_uint(bA.x), __float_as_uint(bA.y));
                mma8(acc1, a0, a1, a2, a3, __float_as_uint(bB.x), __float_as_uint(bB.y));
            }
        }

        const int nb = (zn * N8B + nt * 2) * 8 + tig * 2;
        if (v0) {
            float* o = outRaw + ((((size_t)b * D + (d0 + dl0)) * H + h0) * 3 + w0) * OCTOT + nb;
            *(float2*)o = make_float2(acc0[0], acc0[1]);
            *(float2*)(o + 8) = make_float2(acc1[0], acc1[1]);
        }
        if (v1) {
            float* o = outRaw + ((((size_t)b * D + (d0 + dl1)) * H + h1) * 3 + w1) * OCTOT + nb;
            *(float2*)o = make_float2(acc0[2], acc0[3]);
            *(float2*)(o + 8) = make_float2(acc1[2], acc1[3]);
        }
    }
}

// pool conv3 raw -> g_buf3 (bias+relu)
__global__ __launch_bounds__(256) void pool3_kernel(const float* __restrict__ b3)
{
    const int i = blockIdx.x * 256 + threadIdx.x;
    if (i >= B_SZ * 3 * 9 * 3 * 64) return;
    const int c = i & 63; int r = i >> 6;
    const int w = r % 3; r /= 3;
    const int ph = r % 9; r /= 9;
    const int pd = r % 3; const int b = r / 3;
    const float* p = g_p3 + ((((size_t)b * 6 + 2 * pd) * 18 + 2 * ph) * 3 + w) * 64 + c;
    const int sd = 18 * 3 * 64, sh = 3 * 64;
    const float m = fmaxf(fmaxf(p[0], p[sd]), fmaxf(p[sh], p[sd + sh]));
    g_buf3[i] = fmaxf(m + __ldg(&b3[c]), 0.f);
}

// ---------------------------------------------------------------------------
// prep: mean over 81 positions -> h, ih_const, h2
// ---------------------------------------------------------------------------
__global__ __launch_bounds__(256) void prep_kernel(
    const float* __restrict__ b_init_h, const float* __restrict__ bih1,
    const float* __restrict__ bhh1, const float* __restrict__ b_init_h2)
{
    __shared__ __align__(16) float ms[64];
    __shared__ __align__(16) float hsh[256];
    const int b = blockIdx.x, j = threadIdx.x;
    if (j < 64) {
        float s = 0.f;
        const float* p = g_buf3 + (size_t)b * FLATN + j;
        for (int q = 0; q < 81; q++) s += p[q * 64];
        ms[j] = s * (1.f / 81.f);
    }
    __syncthreads();
    ull aA = 0ull, aB = 0ull;
#pragma unroll
    for (int k4 = 0; k4 < 16; k4++) {
        const ulonglong2 wa = g_wAq[k4 * 256 + j];
        const ulonglong2 wb = g_wBq[k4 * 256 + j];
        const ulonglong2 mv = *(const ulonglong2*)&ms[k4 * 4];
        fma2(aA, wa.x, mv.x); fma2(aA, wa.y, mv.y);
        fma2(aB, wb.x, mv.x); fma2(aB, wb.y, mv.y);
    }
    const float2 uA = upk(aA);
    const float2 uB = upk(aB);
    const float h = uA.x + uA.y + b_init_h[j];
    g_h[(size_t)b * HID + j] = h;
    g_ih[(size_t)b * HID + j] = uB.x + uB.y + bih1[j] + bhh1[j];
    hsh[j] = h;
    __syncthreads();
    ull aC = 0ull;
#pragma unroll 8
    for (int k4 = 0; k4 < 64; k4++) {
        const ulonglong2 wc = g_wCq[k4 * 256 + j];
        const ulonglong2 hv = *(const ulonglong2*)&hsh[k4 * 4];
        fma2(aC, wc.x, hv.x); fma2(aC, wc.y, hv.y);
    }
    const float2 uC = upk(aC);
    g_h2[(size_t)b * HID + j] = uC.x + uC.y + b_init_h2[j];
}

// ---------------------------------------------------------------------------
// 512 threads/block. Blocks 0..63: RNN, 8 rows (two 4-row groups);
// blocks 64..127: lin1, 8 rows.
// ---------------------------------------------------------------------------
__global__ __launch_bounds__(512) void rnn_lin1_kernel(
    const float* __restrict__ bih2, const float* __restrict__ bhh2,
    const float* __restrict__ w_fc, const float* __restrict__ b_fc,
    const float* __restrict__ b_lin1, float* __restrict__ pred_out)
{
    __shared__ __align__(16) float sm[6400];
    const int tid = threadIdx.x;
    const int rg = tid >> 8;
    const int j = tid & 255;

    if (blockIdx.x < 64) {
        float* h_s  = sm;
        float* h2_s = sm + 2048;
        float* ih_s = sm + 4096;
        float* red  = sm + 6144;
        const int r0 = blockIdx.x * 8;
        const int warp = tid >> 5, lane = tid & 31;

#pragma unroll
        for (int r = 0; r < 4; r++) {
            const int row = rg * 4 + r;
            h_s[row * 256 + j]  = g_h[(size_t)(r0 + row) * HID + j];
            h2_s[row * 256 + j] = g_h2[(size_t)(r0 + row) * HID + j];
            ih_s[row * 256 + j] = g_ih[(size_t)(r0 + row) * HID + j];
        }
        const float bias2 = bih2[j] + bhh2[j];
        const float wf = w_fc[j];
        const float bfc = b_fc[0];
        __syncthreads();

        const ulonglong2* W1 = g_wt;
        const ulonglong2* W2 = g_wt + 16384;
        const ulonglong2* W3 = g_wt + 32768;

        for (int t = 0; t < TLEN; t++) {
            ull a1[4];
#pragma unroll
            for (int r = 0; r < 4; r++) a1[r] = 0ull;
#pragma unroll 4
            for (int k4 = 0; k4 < 64; k4++) {
                const ulonglong2 wv = W1[k4 * 256 + j];
#pragma unroll
                for (int r = 0; r < 4; r++) {
                    const ulonglong2 hv = *(const ulonglong2*)&h_s[(rg * 4 + r) * 256 + k4 * 4];
                    fma2(a1[r], wv.x, hv.x);
                    fma2(a1[r], wv.y, hv.y);
                }
            }
            float hn[4];
#pragma unroll
            for (int r = 0; r < 4; r++) {
                const float2 u = upk(a1[r]);
                hn[r] = tanhf(ih_s[(rg * 4 + r) * 256 + j] + u.x + u.y);
            }
            __syncthreads();
#pragma unroll
            for (int r = 0; r < 4; r++) h_s[(rg * 4 + r) * 256 + j] = hn[r];
            __syncthreads();

            ull a2[4];
#pragma unroll
            for (int r = 0; r < 4; r++) a2[r] = 0ull;
#pragma unroll 2
            for (int k4 = 0; k4 < 64; k4++) {
                const ulonglong2 wv2 = W2[k4 * 256 + j];
                const ulonglong2 wv3 = W3[k4 * 256 + j];
#pragma unroll
                for (int r = 0; r < 4; r++) {
                    const ulonglong2 hv = *(const ulonglong2*)&h_s[(rg * 4 + r) * 256 + k4 * 4];
                    const ulonglong2 gv = *(const ulonglong2*)&h2_s[(rg * 4 + r) * 256 + k4 * 4];
                    fma2(a2[r], wv2.x, hv.x);
                    fma2(a2[r], wv2.y, hv.y);
                    fma2(a2[r], wv3.x, gv.x);
                    fma2(a2[r], wv3.y, gv.y);
                }
            }
            float h2n[4];
#pragma unroll
            for (int r = 0; r < 4; r++) {
                const float2 u = upk(a2[r]);
                h2n[r] = tanhf(bias2 + u.x + u.y);
            }
            __syncthreads();
#pragma unroll
            for (int r = 0; r < 4; r++) h2_s[(rg * 4 + r) * 256 + j] = h2n[r];

#pragma unroll
            for (int r = 0; r < 4; r++) {
                float v = h2n[r] * wf;
                v += __shfl_down_sync(0xffffffffu, v, 16);
                v += __shfl_down_sync(0xffffffffu, v, 8);
                v += __shfl_down_sync(0xffffffffu, v, 4);
                v += __shfl_down_sync(0xffffffffu, v, 2);
                v += __shfl_down_sync(0xffffffffu, v, 1);
                if (lane == 0) red[warp * 4 + r] = v;
            }
            __syncthreads();
            if (tid < 8) {
                const int g = tid >> 2;
                float s = bfc;
#pragma unroll
                for (int w = 0; w < 8; w++) s += red[((g << 3) + w) * 4 + (tid & 3)];
                pred_out[(size_t)(r0 + tid) * TLEN + t] = s;
            }
            __syncthreads();
        }
    } else {
        float* fs = sm;    // [8][648]
        const int r0 = (blockIdx.x - 64) * 8;
        ull acc[4];
#pragma unroll
        for (int r = 0; r < 4; r++) acc[r] = 0ull;

        for (int kb = 0; kb < FLATN; kb += 648) {
            __syncthreads();
            for (int i = tid; i < 8 * 648; i += 512) {
                const int r = i / 648, k = i - r * 648;
                fs[i] = g_buf3[(size_t)(r0 + r) * FLATN + kb + k];
            }
            __syncthreads();
            const int k4b = kb / 4;
#pragma unroll 2
            for (int k4 = 0; k4 < 162; k4++) {
                const ulonglong2 wv = g_wl1t[(k4b + k4) * 256 + j];
#pragma unroll
                for (int r = 0; r < 4; r++) {
                    const ulonglong2 hv = *(const ulonglong2*)&fs[(rg * 4 + r) * 648 + k4 * 4];
                    fma2(acc[r], wv.x, hv.x);
                    fma2(acc[r], wv.y, hv.y);
                }
            }
        }
        const float bb = b_lin1[j];
#pragma unroll
        for (int r = 0; r < 4; r++) {
            const float2 u = upk(acc[r]);
            g_t1[(size_t)(r0 + rg * 4 + r) * HID + j] = tanhf(u.x + u.y + bb);
        }
    }
}

__global__ __launch_bounds__(384) void lin2_kernel(
    const float* __restrict__ w_lin2, const float* __restrict__ b_lin2,
    float* __restrict__ outc)
{
    const int b = blockIdx.x;
    const int m = threadIdx.x >> 5;
    const int lane = threadIdx.x & 31;
    const float* tr = &g_t1[(size_t)b * HID];
    const float* wr = &w_lin2[(size_t)m * HID];
    float s = 0.f;
    for (int k = lane; k < HID; k += 32) s += tr[k] * wr[k];
    s += __shfl_down_sync(0xffffffffu, s, 16);
    s += __shfl_down_sync(0xffffffffu, s, 8);
    s += __shfl_down_sync(0xffffffffu, s, 4);
    s += __shfl_down_sync(0xffffffffu, s, 2);
    s += __shfl_down_sync(0xffffffffu, s, 1);
    if (lane == 0) outc[b * 12 + m] = s + b_lin2[m];
}

// ---------------------------------------------------------------------------

extern "C" void kernel_launch(void* const* d_in, const int* in_sizes, int n_in,
                              void* d_out, int out_size)
{
    const float* x        = (const float*)d_in[0];
    const float* w1       = (const float*)d_in[1];
    const float* b1       = (const float*)d_in[2];
    const float* w2       = (const float*)d_in[3];
    const float* b2       = (const float*)d_in[4];
    const float* w3       = (const float*)d_in[5];
    const float* b3       = (const float*)d_in[6];
    const float* wih1     = (const float*)d_in[7];
    const float* whh1     = (const float*)d_in[8];
    const float* bih1     = (const float*)d_in[9];
    const float* bhh1     = (const float*)d_in[10];
    const float* wih2     = (const float*)d_in[11];
    const float* whh2     = (const float*)d_in[12];
    const float* bih2     = (const float*)d_in[13];
    const float* bhh2     = (const float*)d_in[14];
    const float* w_init_h = (const float*)d_in[15];
    const float* b_init_h = (const float*)d_in[16];
    const float* w_init_h2= (const float*)d_in[17];
    const float* b_init_h2= (const float*)d_in[18];
    const float* w_fc     = (const float*)d_in[19];
    const float* b_fc     = (const float*)d_in[20];
    const float* w_lin1   = (const float*)d_in[21];
    const float* b_lin1   = (const float*)d_in[22];
    const float* w_lin2   = (const float*)d_in[23];
    const float* b_lin2   = (const float*)d_in[24];

    float* pred = (float*)d_out;
    float* outc = pred + B_SZ * TLEN;

    float *buf1, *p2, *p3;
    ull* wc1;
    float2 *f2, *f3;
    cudaGetSymbolAddress((void**)&buf1, g_buf1);
    cudaGetSymbolAddress((void**)&p2, g_p2);
    cudaGetSymbolAddress((void**)&p3, g_p3);
    cudaGetSymbolAddress((void**)&wc1, g_wc1);
    cudaGetSymbolAddress((void**)&f2, g_f2);
    cudaGetSymbolAddress((void**)&f3, g_f3);

    pack_convw_kernel<<<11, 256>>>(w1);
    pack_frag_kernel<<<135, 256>>>(w2, w3);
    pack_weights_kernel<<<1584, 256>>>(whh1, wih2, whh2, w_init_h, wih1,
                                       w_init_h2, w_lin1);

    // conv1: SIMT f32x2, D split in 2 halves (exact fp32)
    auto k1 = &conv_k<6, 16, 24, 72, 6, 2>;
    const int sm1 = 13 * 72 * 3 * 6 * 4 + 6 * 27 * 16 * 8;   // 88128
    cudaFuncSetAttribute(k1, cudaFuncAttributeMaxDynamicSharedMemorySize, sm1);
    k1<<<dim3(B_SZ, 2), 576, sm1>>>(x, wc1, b1, buf1);

    // conv2: tf32 mma v2 (ICR=16, D=12, H=36, DR=2, KC=2, NT=2, N8TOT=4)
    auto k2 = &conv_mma2<16, 12, 36, 2, 2, 2, 4, false>;
    const int sm2 = 4 * 38 * 5 * 16 * 4 + 27 * 2 * 4 * 32 * 8;   // 48640+55296=103936
    cudaFuncSetAttribute(k2, cudaFuncAttributeMaxDynamicSharedMemorySize, sm2);
    k2<<<dim3(B_SZ, 6, 1), 256, sm2>>>(buf1, b1, f2, p2);

    // conv3: tf32 mma v2 (ICR=32, D=6, H=18, DR=2, KC=4, NT=1, N8TOT=8), n-quarters
    auto k3 = &conv_mma2<32, 6, 18, 2, 4, 1, 8, true>;
    const int sm3 = 4 * 20 * 5 * 32 * 4 + 27 * 4 * 2 * 32 * 8;   // 51200+55296=106496
    cudaFuncSetAttribute(k3, cudaFuncAttributeMaxDynamicSharedMemorySize, sm3);
    k3<<<dim3(B_SZ, 3, 4), 256, sm3>>>(p2, b2, f3, p3);

    pool3_kernel<<<(B_SZ * 3 * 9 * 3 * 64 + 255) / 256, 256>>>(b3);

    prep_kernel<<<B_SZ, 256>>>(b_init_h, bih1, bhh1, b_init_h2);
    rnn_lin1_kernel<<<128, 512>>>(bih2, bhh2, w_fc, b_fc, b_lin1, pred);
    lin2_kernel<<<B_SZ, 384>>>(w_lin2, b_lin2, outc);

    (void)in_sizes; (void)n_in; (void)out_size;
}

// round 10
// speedup vs baseline: 1.2633x; 1.2633x over previous
#include <cuda_runtime.h>
#include <cuda_bf16.h>
#include <cstdint>

#define B_SZ 512
#define HID 256
#define TLEN 23
#define FLATN 5184

typedef unsigned long long ull;

// ---------------- scratch ----------------
__device__ float g_buf1[B_SZ * 12 * 36 * 3 * 16];   // conv1 pooled NDHWC
__device__ float g_buf2[B_SZ * 6 * 18 * 3 * 32];    // conv2 pooled NDHWC
__device__ float g_buf3[B_SZ * 3 * 9 * 3 * 64];     // conv3 pooled NDHWC == flat
__device__ float g_h[B_SZ * HID];
__device__ float g_h2[B_SZ * HID];
__device__ float g_ih[B_SZ * HID];
__device__ float g_t1[B_SZ * HID];

// conv weights, f32x2-dup, layout [(ic*27 + kh*9 + kd*3 + kw)*OC + oc]
__device__ ull g_wc1[162 * 16];
__device__ ull g_wc2[432 * 32];
__device__ ull g_wc3[864 * 64];

// matmul weights packed-transposed [k4][j]
__device__ ulonglong2 g_wt[3 * 64 * 256];
__device__ ulonglong2 g_wAq[16 * 256];
__device__ ulonglong2 g_wBq[16 * 256];
__device__ ulonglong2 g_wCq[64 * 256];
__device__ ulonglong2 g_wl1t[1296 * 256];

// ---------------- f32x2 helpers ----------------
__device__ __forceinline__ void fma2(ull& acc, ull a, ull b) {
    asm("fma.rn.f32x2 %0, %1, %2, %0;" : "+l"(acc) : "l"(a), "l"(b));
}
__device__ __forceinline__ ull pk2(float lo, float hi) {
    ull r; asm("mov.b64 %0, {%1,%2};" : "=l"(r) : "f"(lo), "f"(hi)); return r;
}
__device__ __forceinline__ float2 upk(ull v) {
    float lo, hi; asm("mov.b64 {%0,%1}, %2;" : "=f"(lo), "=f"(hi) : "l"(v));
    return make_float2(lo, hi);
}
// (hi of a, lo of b)
__device__ __forceinline__ ull mixp(ull a, ull b) {
    ull r;
    asm("{\n\t.reg .f32 al, ah, bl, bh;\n\t"
        "mov.b64 {al, ah}, %1;\n\t"
        "mov.b64 {bl, bh}, %2;\n\t"
        "mov.b64 %0, {ah, bl};\n\t}"
        : "=l"(r) : "l"(a), "l"(b));
    return r;
}

// ---------------- weight packers ----------------
// conv: wd[(ic*27 + kh*9 + kd*3 + kw)*OC + oc] = dup(w[oc][ic][kd][kh][kw])
__global__ __launch_bounds__(256) void pack_convw_kernel(
    const float* __restrict__ w1, const float* __restrict__ w2,
    const float* __restrict__ w3)
{
    const int idx = blockIdx.x * 256 + threadIdx.x;
    if (idx >= 71712) return;
    const float* src; ull* dst; int OC, ICNT, local;
    if (idx < 2592)       { local = idx;         src = w1; dst = g_wc1; OC = 16; ICNT = 6; }
    else if (idx < 16416) { local = idx - 2592;  src = w2; dst = g_wc2; OC = 32; ICNT = 16; }
    else                  { local = idx - 16416; src = w3; dst = g_wc3; OC = 64; ICNT = 32; }
    const int oc = local % OC;
    const int kk = local / OC;           // ic*27 + kh*9 + kd*3 + kw
    const int ic = kk / 27, r = kk % 27;
    const int kh = r / 9, r2 = r % 9;
    const int kd = r2 / 3, kw = r2 % 3;
    const float v = src[((size_t)oc * ICNT + ic) * 27 + kd * 9 + kh * 3 + kw];
    dst[local] = pk2(v, v);
}

__global__ __launch_bounds__(256) void pack_weights_kernel(
    const float* __restrict__ whh1, const float* __restrict__ wih2,
    const float* __restrict__ whh2, const float* __restrict__ w_init_h,
    const float* __restrict__ wih1, const float* __restrict__ w_init_h2,
    const float* __restrict__ w_lin1)
{
    const int idx = blockIdx.x * 256 + threadIdx.x;   // < 405504
    const float* src; ulonglong2* dst; int K; int local;
    if (idx < 49152)      { int m = idx / 16384; local = idx % 16384;
                            src = (m == 0) ? whh1 : ((m == 1) ? wih2 : whh2);
                            dst = g_wt + m * 16384; K = 256; }
    else if (idx < 53248) { local = idx - 49152; src = w_init_h;  dst = g_wAq;  K = 64; }
    else if (idx < 57344) { local = idx - 53248; src = wih1;      dst = g_wBq;  K = 64; }
    else if (idx < 73728) { local = idx - 57344; src = w_init_h2; dst = g_wCq;  K = 256; }
    else                  { local = idx - 73728; src = w_lin1;    dst = g_wl1t; K = 5184; }
    const int j = local % 256;
    const int k4 = local / 256;
    const float4 v = *(const float4*)&src[(size_t)j * K + k4 * 4];
    ulonglong2 o; o.x = pk2(v.x, v.y); o.y = pk2(v.z, v.w);
    dst[local] = o;
}

// ---------------------------------------------------------------------------
// Hybrid conv: d-innermost zero-padded slab (LDS.64 x-pairs, no d-predicates)
// + smem-resident weights (coalesced LDS.64).
// Block = (batch, pd-group of 3). 576 = OC*H2 threads; thread = (oc, ph).
// xs[(j*IC + ic)*10 + slot], slot = conv-d - g0, slots 0..7 valid, 8..9 pad.
// ---------------------------------------------------------------------------
template <int IC, int OC, int D, int H, int WCH, bool TRANSIN>
__global__ __launch_bounds__(576, 1) void conv_hyb(
    const float* __restrict__ x, const ull* __restrict__ wg,
    const float* __restrict__ bias, float* __restrict__ out)
{
    constexpr int H2 = H / 2;
    constexpr int D2 = D / 2;
    constexpr int ROW = H * 3 * IC;
    constexpr int WSZ = WCH * 27 * OC;   // ull count per chunk
    constexpr int NCH = IC / WCH;
    extern __shared__ float sm_[];
    float* xs = sm_;                     // ROW * 10 floats
    ull* ws = (ull*)(sm_ + ROW * 10);    // WSZ ulls

    const int b = blockIdx.x;
    const int pd0 = blockIdx.y * 3;
    const int g0 = 2 * pd0 - 1;
    const int tid = threadIdx.x;

    // ---- slab fill (zero-pad out-of-range d) ----
    if (TRANSIN) {
        // src NCDHW: [IC][D][H*3]
        const float* xb = x + (size_t)b * IC * D * H * 3;
        for (int i = tid; i < IC * 8 * H * 3; i += 576) {
            const int ic = i / (8 * H * 3);
            const int r = i - ic * (8 * H * 3);
            const int slot = r / (H * 3);
            const int j2 = r - slot * (H * 3);
            const int d = g0 + slot;
            const float v = ((unsigned)d < (unsigned)D)
                          ? xb[(ic * D + d) * H * 3 + j2] : 0.f;
            xs[(j2 * IC + ic) * 10 + slot] = v;
        }
    } else {
        // src NDHWC: [D][H*3*IC]
        for (int i = tid; i < 8 * ROW; i += 576) {
            const int slot = i / ROW;
            const int j = i - slot * ROW;
            const int d = g0 + slot;
            xs[j * 10 + slot] = ((unsigned)d < (unsigned)D)
                              ? x[((size_t)b * D + d) * ROW + j] : 0.f;
        }
    }
    if (NCH == 1) {
        const ulonglong2* wsrc = (const ulonglong2*)wg;
        ulonglong2* wdst = (ulonglong2*)ws;
        for (int i = tid; i < WSZ / 2; i += 576) wdst[i] = wsrc[i];
    }
    __syncthreads();

    const int oc = tid % OC;
    const int ph = tid / OC;
    const bool hsafe = (ph > 0) && (ph < H2 - 1);
    const float bv = __ldg(&bias[oc]);

    ull acc[3][2][3];
#pragma unroll
    for (int p = 0; p < 3; p++)
#pragma unroll
        for (int c = 0; c < 2; c++)
#pragma unroll
            for (int w = 0; w < 3; w++) acc[p][c][w] = 0ull;

#pragma unroll 1
    for (int ch = 0; ch < NCH; ch++) {
        if (NCH > 1) {
            __syncthreads();
            const ulonglong2* wsrc = (const ulonglong2*)(wg + (size_t)ch * WSZ);
            ulonglong2* wdst = (ulonglong2*)ws;
            for (int i = tid; i < WSZ / 2; i += 576) wdst[i] = wsrc[i];
            __syncthreads();
        }
#pragma unroll 1
        for (int icl = 0; icl < WCH; icl++) {
            const int icg = ch * WCH + icl;
            const ull* wic = ws + icl * 27 * OC + oc;
#pragma unroll
            for (int hxr = 0; hxr < 4; hxr++) {
                const int hx = 2 * ph - 1 + hxr;
                const bool hok = hsafe || ((unsigned)hx < (unsigned)H);
                ull e[3][4], od[3][3];
#pragma unroll
                for (int c = 0; c < 3; c++) {
                    if (hok) {
                        const ull* rp = (const ull*)(xs + ((hx * 3 + c) * IC + icg) * 10);
                        e[c][0] = rp[0]; e[c][1] = rp[1]; e[c][2] = rp[2]; e[c][3] = rp[3];
                    } else {
                        e[c][0] = e[c][1] = e[c][2] = e[c][3] = 0ull;
                    }
                    od[c][0] = mixp(e[c][0], e[c][1]);
                    od[c][1] = mixp(e[c][1], e[c][2]);
                    od[c][2] = mixp(e[c][2], e[c][3]);
                }
#pragma unroll
                for (int chh = 0; chh < 2; chh++) {
                    const int kh = hxr - chh;
                    if (kh < 0 || kh > 2) continue;
#pragma unroll
                    for (int kd = 0; kd < 3; kd++) {
                        const ull* wp = wic + (kh * 9 + kd * 3) * OC;
                        const ull W0 = wp[0];
                        const ull W1 = wp[OC];
                        const ull W2 = wp[2 * OC];
#pragma unroll
                        for (int p = 0; p < 3; p++) {
                            ull x0, x1, x2;
                            if (kd == 0)      { x0 = e[0][p];     x1 = e[1][p];     x2 = e[2][p]; }
                            else if (kd == 1) { x0 = od[0][p];    x1 = od[1][p];    x2 = od[2][p]; }
                            else              { x0 = e[0][p + 1]; x1 = e[1][p + 1]; x2 = e[2][p + 1]; }
                            fma2(acc[p][chh][0], W1, x0);
                            fma2(acc[p][chh][0], W2, x1);
                            fma2(acc[p][chh][1], W0, x0);
                            fma2(acc[p][chh][1], W1, x1);
                            fma2(acc[p][chh][1], W2, x2);
                            fma2(acc[p][chh][2], W0, x1);
                            fma2(acc[p][chh][2], W1, x2);
                        }
                    }
                }
            }
        }
    }

    // ---- pool (d-pair halves x 2 h) + bias + relu, NDHWC store ----
#pragma unroll
    for (int p = 0; p < 3; p++) {
        const int pd = pd0 + p;
#pragma unroll
        for (int pw = 0; pw < 3; pw++) {
            const float2 u0 = upk(acc[p][0][pw]);
            const float2 u1 = upk(acc[p][1][pw]);
            float m = fmaxf(fmaxf(u0.x, u0.y), fmaxf(u1.x, u1.y)) + bv;
            out[((((size_t)b * D2 + pd) * H2 + ph) * 3 + pw) * OC + oc] = fmaxf(m, 0.f);
        }
    }
}

// ---------------------------------------------------------------------------
// prep: mean over 81 positions -> h, ih_const, h2
// ---------------------------------------------------------------------------
__global__ __launch_bounds__(256) void prep_kernel(
    const float* __restrict__ b_init_h, const float* __restrict__ bih1,
    const float* __restrict__ bhh1, const float* __restrict__ b_init_h2)
{
    __shared__ __align__(16) float ms[64];
    __shared__ __align__(16) float hsh[256];
    const int b = blockIdx.x, j = threadIdx.x;
    if (j < 64) {
        float s = 0.f;
        const float* p = g_buf3 + (size_t)b * FLATN + j;
        for (int q = 0; q < 81; q++) s += p[q * 64];
        ms[j] = s * (1.f / 81.f);
    }
    __syncthreads();
    ull aA = 0ull, aB = 0ull;
#pragma unroll
    for (int k4 = 0; k4 < 16; k4++) {
        const ulonglong2 wa = g_wAq[k4 * 256 + j];
        const ulonglong2 wb = g_wBq[k4 * 256 + j];
        const ulonglong2 mv = *(const ulonglong2*)&ms[k4 * 4];
        fma2(aA, wa.x, mv.x); fma2(aA, wa.y, mv.y);
        fma2(aB, wb.x, mv.x); fma2(aB, wb.y, mv.y);
    }
    const float2 uA = upk(aA);
    const float2 uB = upk(aB);
    const float h = uA.x + uA.y + b_init_h[j];
    g_h[(size_t)b * HID + j] = h;
    g_ih[(size_t)b * HID + j] = uB.x + uB.y + bih1[j] + bhh1[j];
    hsh[j] = h;
    __syncthreads();
    ull aC = 0ull;
#pragma unroll 8
    for (int k4 = 0; k4 < 64; k4++) {
        const ulonglong2 wc = g_wCq[k4 * 256 + j];
        const ulonglong2 hv = *(const ulonglong2*)&hsh[k4 * 4];
        fma2(aC, wc.x, hv.x); fma2(aC, wc.y, hv.y);
    }
    const float2 uC = upk(aC);
    g_h2[(size_t)b * HID + j] = uC.x + uC.y + b_init_h2[j];
}

// ---------------------------------------------------------------------------
// 512 threads/block. Blocks 0..63: RNN, 8 rows (two 4-row groups);
// blocks 64..127: lin1, 8 rows.
// ---------------------------------------------------------------------------
__global__ __launch_bounds__(512) void rnn_lin1_kernel(
    const float* __restrict__ bih2, const float* __restrict__ bhh2,
    const float* __restrict__ w_fc, const float* __restrict__ b_fc,
    const float* __restrict__ b_lin1, float* __restrict__ pred_out)
{
    __shared__ __align__(16) float sm[6400];
    const int tid = threadIdx.x;
    const int rg = tid >> 8;
    const int j = tid & 255;

    if (blockIdx.x < 64) {
        float* h_s  = sm;
        float* h2_s = sm + 2048;
        float* ih_s = sm + 4096;
        float* red  = sm + 6144;
        const int r0 = blockIdx.x * 8;
        const int warp = tid >> 5, lane = tid & 31;

#pragma unroll
        for (int r = 0; r < 4; r++) {
            const int row = rg * 4 + r;
            h_s[row * 256 + j]  = g_h[(size_t)(r0 + row) * HID + j];
            h2_s[row * 256 + j] = g_h2[(size_t)(r0 + row) * HID + j];
            ih_s[row * 256 + j] = g_ih[(size_t)(r0 + row) * HID + j];
        }
        const float bias2 = bih2[j] + bhh2[j];
        const float wf = w_fc[j];
        const float bfc = b_fc[0];
        __syncthreads();

        const ulonglong2* W1 = g_wt;
        const ulonglong2* W2 = g_wt + 16384;
        const ulonglong2* W3 = g_wt + 32768;

        for (int t = 0; t < TLEN; t++) {
            ull a1[4];
#pragma unroll
            for (int r = 0; r < 4; r++) a1[r] = 0ull;
#pragma unroll 4
            for (int k4 = 0; k4 < 64; k4++) {
                const ulonglong2 wv = W1[k4 * 256 + j];
#pragma unroll
                for (int r = 0; r < 4; r++) {
                    const ulonglong2 hv = *(const ulonglong2*)&h_s[(rg * 4 + r) * 256 + k4 * 4];
                    fma2(a1[r], wv.x, hv.x);
                    fma2(a1[r], wv.y, hv.y);
                }
            }
            float hn[4];
#pragma unroll
            for (int r = 0; r < 4; r++) {
                const float2 u = upk(a1[r]);
                hn[r] = tanhf(ih_s[(rg * 4 + r) * 256 + j] + u.x + u.y);
            }
            __syncthreads();
#pragma unroll
            for (int r = 0; r < 4; r++) h_s[(rg * 4 + r) * 256 + j] = hn[r];
            __syncthreads();

            ull a2[4];
#pragma unroll
            for (int r = 0; r < 4; r++) a2[r] = 0ull;
#pragma unroll 2
            for (int k4 = 0; k4 < 64; k4++) {
                const ulonglong2 wv2 = W2[k4 * 256 + j];
                const ulonglong2 wv3 = W3[k4 * 256 + j];
#pragma unroll
                for (int r = 0; r < 4; r++) {
                    const ulonglong2 hv = *(const ulonglong2*)&h_s[(rg * 4 + r) * 256 + k4 * 4];
                    const ulonglong2 gv = *(const ulonglong2*)&h2_s[(rg * 4 + r) * 256 + k4 * 4];
                    fma2(a2[r], wv2.x, hv.x);
                    fma2(a2[r], wv2.y, hv.y);
                    fma2(a2[r], wv3.x, gv.x);
                    fma2(a2[r], wv3.y, gv.y);
                }
            }
            float h2n[4];
#pragma unroll
            for (int r = 0; r < 4; r++) {
                const float2 u = upk(a2[r]);
                h2n[r] = tanhf(bias2 + u.x + u.y);
            }
            __syncthreads();
#pragma unroll
            for (int r = 0; r < 4; r++) h2_s[(rg * 4 + r) * 256 + j] = h2n[r];

#pragma unroll
            for (int r = 0; r < 4; r++) {
                float v = h2n[r] * wf;
                v += __shfl_down_sync(0xffffffffu, v, 16);
                v += __shfl_down_sync(0xffffffffu, v, 8);
                v += __shfl_down_sync(0xffffffffu, v, 4);
                v += __shfl_down_sync(0xffffffffu, v, 2);
                v += __shfl_down_sync(0xffffffffu, v, 1);
                if (lane == 0) red[warp * 4 + r] = v;
            }
            __syncthreads();
            if (tid < 8) {
                const int g = tid >> 2;
                float s = bfc;
#pragma unroll
                for (int w = 0; w < 8; w++) s += red[((g << 3) + w) * 4 + (tid & 3)];
                pred_out[(size_t)(r0 + tid) * TLEN + t] = s;
            }
            __syncthreads();
        }
    } else {
        float* fs = sm;    // [8][648]
        const int r0 = (blockIdx.x - 64) * 8;
        ull acc[4];
#pragma unroll
        for (int r = 0; r < 4; r++) acc[r] = 0ull;

        for (int kb = 0; kb < FLATN; kb += 648) {
            __syncthreads();
            for (int i = tid; i < 8 * 648; i += 512) {
                const int r = i / 648, k = i - r * 648;
                fs[i] = g_buf3[(size_t)(r0 + r) * FLATN + kb + k];
            }
            __syncthreads();
            const int k4b = kb / 4;
#pragma unroll 2
            for (int k4 = 0; k4 < 162; k4++) {
                const ulonglong2 wv = g_wl1t[(k4b + k4) * 256 + j];
#pragma unroll
                for (int r = 0; r < 4; r++) {
                    const ulonglong2 hv = *(const ulonglong2*)&fs[(rg * 4 + r) * 648 + k4 * 4];
                    fma2(acc[r], wv.x, hv.x);
                    fma2(acc[r], wv.y, hv.y);
                }
            }
        }
        const float bb = b_lin1[j];
#pragma unroll
        for (int r = 0; r < 4; r++) {
            const float2 u = upk(acc[r]);
            g_t1[(size_t)(r0 + rg * 4 + r) * HID + j] = tanhf(u.x + u.y + bb);
        }
    }
}

__global__ __launch_bounds__(384) void lin2_kernel(
    const float* __restrict__ w_lin2, const float* __restrict__ b_lin2,
    float* __restrict__ outc)
{
    const int b = blockIdx.x;
    const int m = threadIdx.x >> 5;
    const int lane = threadIdx.x & 31;
    const float* tr = &g_t1[(size_t)b * HID];
    const float* wr = &w_lin2[(size_t)m * HID];
    float s = 0.f;
    for (int k = lane; k < HID; k += 32) s += tr[k] * wr[k];
    s += __shfl_down_sync(0xffffffffu, s, 16);
    s += __shfl_down_sync(0xffffffffu, s, 8);
    s += __shfl_down_sync(0xffffffffu, s, 4);
    s += __shfl_down_sync(0xffffffffu, s, 2);
    s += __shfl_down_sync(0xffffffffu, s, 1);
    if (lane == 0) outc[b * 12 + m] = s + b_lin2[m];
}

// ---------------------------------------------------------------------------

extern "C" void kernel_launch(void* const* d_in, const int* in_sizes, int n_in,
                              void* d_out, int out_size)
{
    const float* x        = (const float*)d_in[0];
    const float* w1       = (const float*)d_in[1];
    const float* b1       = (const float*)d_in[2];
    const float* w2       = (const float*)d_in[3];
    const float* b2       = (const float*)d_in[4];
    const float* w3       = (const float*)d_in[5];
    const float* b3       = (const float*)d_in[6];
    const float* wih1     = (const float*)d_in[7];
    const float* whh1     = (const float*)d_in[8];
    const float* bih1     = (const float*)d_in[9];
    const float* bhh1     = (const float*)d_in[10];
    const float* wih2     = (const float*)d_in[11];
    const float* whh2     = (const float*)d_in[12];
    const float* bih2     = (const float*)d_in[13];
    const float* bhh2     = (const float*)d_in[14];
    const float* w_init_h = (const float*)d_in[15];
    const float* b_init_h = (const float*)d_in[16];
    const float* w_init_h2= (const float*)d_in[17];
    const float* b_init_h2= (const float*)d_in[18];
    const float* w_fc     = (const float*)d_in[19];
    const float* b_fc     = (const float*)d_in[20];
    const float* w_lin1   = (const float*)d_in[21];
    const float* b_lin1   = (const float*)d_in[22];
    const float* w_lin2   = (const float*)d_in[23];
    const float* b_lin2   = (const float*)d_in[24];

    float* pred = (float*)d_out;
    float* outc = pred + B_SZ * TLEN;

    float *buf1, *buf2, *buf3;
    ull *wc1, *wc2, *wc3;
    cudaGetSymbolAddress((void**)&buf1, g_buf1);
    cudaGetSymbolAddress((void**)&buf2, g_buf2);
    cudaGetSymbolAddress((void**)&buf3, g_buf3);
    cudaGetSymbolAddress((void**)&wc1, g_wc1);
    cudaGetSymbolAddress((void**)&wc2, g_wc2);
    cudaGetSymbolAddress((void**)&wc3, g_wc3);

    pack_convw_kernel<<<281, 256>>>(w1, w2, w3);
    pack_weights_kernel<<<1584, 256>>>(whh1, wih2, whh2, w_init_h, wih1,
                                       w_init_h2, w_lin1);

    // hybrid convs: d-innermost slab + smem weights
    auto k1 = &conv_hyb<6, 16, 24, 72, 6, true>;     // NCH=1
    auto k2 = &conv_hyb<16, 32, 12, 36, 16, false>;  // NCH=1
    auto k3 = &conv_hyb<32, 64, 6, 18, 8, false>;    // NCH=4
    const int sm1 = 72 * 3 * 6 * 10 * 4 + 6 * 27 * 16 * 8;     // 51840+20736=72576
    const int sm2 = 36 * 3 * 16 * 10 * 4 + 16 * 27 * 32 * 8;   // 69120+110592=179712
    const int sm3 = 18 * 3 * 32 * 10 * 4 + 8 * 27 * 64 * 8;    // 69120+110592=179712
    cudaFuncSetAttribute(k1, cudaFuncAttributeMaxDynamicSharedMemorySize, sm1);
    cudaFuncSetAttribute(k2, cudaFuncAttributeMaxDynamicSharedMemorySize, sm2);
    cudaFuncSetAttribute(k3, cudaFuncAttributeMaxDynamicSharedMemorySize, sm3);

    k1<<<dim3(B_SZ, 4), 576, sm1>>>(x, wc1, b1, buf1);
    k2<<<dim3(B_SZ, 2), 576, sm2>>>(buf1, wc2, b2, buf2);
    k3<<<dim3(B_SZ, 1), 576, sm3>>>(buf2, wc3, b3, buf3);

    prep_kernel<<<B_SZ, 256>>>(b_init_h, bih1, bhh1, b_init_h2);
    rnn_lin1_kernel<<<128, 512>>>(bih2, bhh2, w_fc, b_fc, b_lin1, pred);
    lin2_kernel<<<B_SZ, 384>>>(w_lin2, b_lin2, outc);

    (void)in_sizes; (void)n_in; (void)out_size;
}

// round 12
// speedup vs baseline: 1.5558x; 1.2315x over previous
#include <cuda_runtime.h>
#include <cuda_bf16.h>
#include <cstdint>

#define B_SZ 512
#define HID 256
#define TLEN 23
#define FLATN 5184

typedef unsigned long long ull;

// ---------------- scratch ----------------
__device__ float g_buf1[B_SZ * 12 * 36 * 3 * 16];   // conv1 pooled NDHWC
__device__ float g_p2[B_SZ * 12 * 36 * 3 * 32];     // conv2 RAW pre-pool NDHWC
__device__ float g_p3[B_SZ * 6 * 18 * 3 * 64];      // conv3 RAW pre-pool NDHWC
__device__ float g_buf3[B_SZ * 3 * 9 * 3 * 64];     // conv3 pooled NDHWC == flat
__device__ float g_h[B_SZ * HID];
__device__ float g_h2[B_SZ * HID];
__device__ float g_ih[B_SZ * HID];
__device__ float g_t1[B_SZ * HID];

// conv1 weights transposed + f32x2-dup: [(ic*27 + tap)*16 + oc]
__device__ ull g_wc1[162 * 16];

// tf32 weight fragments, B-fragment order: [((t*KC+kc)*N8TOT + n8)*32 + lane]
__device__ float2 g_f2[27 * 2 * 4 * 32];     // conv2: KC=2, N8TOT=4
__device__ float2 g_f3[27 * 4 * 8 * 32];     // conv3: KC=4, N8TOT=8

// matmul weights packed-transposed [k4][j]
__device__ ulonglong2 g_wt[3 * 64 * 256];
__device__ ulonglong2 g_wAq[16 * 256];
__device__ ulonglong2 g_wBq[16 * 256];
__device__ ulonglong2 g_wCq[64 * 256];
__device__ ulonglong2 g_wl1t[1296 * 256];

// ---------------- helpers ----------------
__device__ __forceinline__ void fma2(ull& acc, ull a, ull b) {
    asm("fma.rn.f32x2 %0, %1, %2, %0;" : "+l"(acc) : "l"(a), "l"(b));
}
__device__ __forceinline__ ull pk2(float lo, float hi) {
    ull r; asm("mov.b64 %0, {%1,%2};" : "=l"(r) : "f"(lo), "f"(hi)); return r;
}
__device__ __forceinline__ float2 upk(ull v) {
    float lo, hi; asm("mov.b64 {%0,%1}, %2;" : "=f"(lo), "=f"(hi) : "l"(v));
    return make_float2(lo, hi);
}
__device__ __forceinline__ uint32_t ctf(float v) {
    uint32_t r; asm("cvt.rna.tf32.f32 %0, %1;" : "=r"(r) : "f"(v)); return r;
}
__device__ __forceinline__ void mma8(float c[4], uint32_t a0, uint32_t a1,
                                     uint32_t a2, uint32_t a3,
                                     uint32_t b0, uint32_t b1) {
    asm("mma.sync.aligned.m16n8k8.row.col.f32.tf32.tf32.f32 "
        "{%0,%1,%2,%3}, {%4,%5,%6,%7}, {%8,%9}, {%0,%1,%2,%3};"
        : "+f"(c[0]), "+f"(c[1]), "+f"(c[2]), "+f"(c[3])
        : "r"(a0), "r"(a1), "r"(a2), "r"(a3), "r"(b0), "r"(b1));
}

// ---------------- weight packers ----------------
__global__ __launch_bounds__(256) void pack_convw_kernel(const float* __restrict__ w1)
{
    const int idx = blockIdx.x * 256 + threadIdx.x;
    if (idx >= 2592) return;
    const int oc = idx % 16, k = idx / 16;
    const float v = w1[(size_t)oc * 162 + k];
    g_wc1[idx] = pk2(v, v);
}

// tf32 B-fragment layout: B[k][n], k = kc*8 + (lane&3) (+4), n = n8*8 + (lane>>2)
__global__ __launch_bounds__(256) void pack_frag_kernel(
    const float* __restrict__ w2, const float* __restrict__ w3)
{
    const int idx = blockIdx.x * 256 + threadIdx.x;
    if (idx < 6912) {                       // conv2
        const int lane = idx & 31; int r = idx >> 5;
        const int n8 = r % 4; r /= 4;
        const int kc = r % 2; const int t = r / 2;
        const int oc = n8 * 8 + (lane >> 2), c = lane & 3;
        const int ic0 = kc * 8 + c, ic1 = ic0 + 4;
        const float v0 = w2[((size_t)oc * 16 + ic0) * 27 + t];
        const float v1 = w2[((size_t)oc * 16 + ic1) * 27 + t];
        g_f2[idx] = make_float2(__uint_as_float(ctf(v0)), __uint_as_float(ctf(v1)));
    } else if (idx < 6912 + 27648) {        // conv3
        const int j = idx - 6912;
        const int lane = j & 31; int r = j >> 5;
        const int n8 = r % 8; r /= 8;
        const int kc = r % 4; const int t = r / 4;
        const int oc = n8 * 8 + (lane >> 2), c = lane & 3;
        const int ic0 = kc * 8 + c, ic1 = ic0 + 4;
        const float v0 = w3[((size_t)oc * 32 + ic0) * 27 + t];
        const float v1 = w3[((size_t)oc * 32 + ic1) * 27 + t];
        g_f3[j] = make_float2(__uint_as_float(ctf(v0)), __uint_as_float(ctf(v1)));
    }
}

__global__ __launch_bounds__(256) void pack_weights_kernel(
    const float* __restrict__ whh1, const float* __restrict__ wih2,
    const float* __restrict__ whh2, const float* __restrict__ w_init_h,
    const float* __restrict__ wih1, const float* __restrict__ w_init_h2,
    const float* __restrict__ w_lin1)
{
    const int idx = blockIdx.x * 256 + threadIdx.x;   // < 405504
    const float* src; ulonglong2* dst; int K; int local;
    if (idx < 49152)      { int m = idx / 16384; local = idx % 16384;
                            src = (m == 0) ? whh1 : ((m == 1) ? wih2 : whh2);
                            dst = g_wt + m * 16384; K = 256; }
    else if (idx < 53248) { local = idx - 49152; src = w_init_h;  dst = g_wAq;  K = 64; }
    else if (idx < 57344) { local = idx - 53248; src = wih1;      dst = g_wBq;  K = 64; }
    else if (idx < 73728) { local = idx - 57344; src = w_init_h2; dst = g_wCq;  K = 256; }
    else                  { local = idx - 73728; src = w_lin1;    dst = g_wl1t; K = 5184; }
    const int j = local % 256;
    const int k4 = local / 256;
    const float4 v = *(const float4*)&src[(size_t)j * K + k4 * 4];
    ulonglong2 o; o.x = pk2(v.x, v.y); o.y = pk2(v.z, v.w);
    dst[local] = o;
}

// ---------------------------------------------------------------------------
// conv1: SIMT f32x2 (exact fp32), D split in 2 halves. Measured 389us.
// ---------------------------------------------------------------------------
template <int IC, int OC, int DSLAB, int H, int WCH, bool SAFE>
__device__ __forceinline__ void conv_acc(
    const float* __restrict__ xs, const ull* __restrict__ ws,
    int oc, int icbase, int dsl, int ph, bool dlo, bool dhi, ull acc[3][2][3])
{
#pragma unroll 1
    for (int icl = 0; icl < WCH; icl++) {
        const float* xb = xs + icbase + icl;
        const ull* wb = ws + icl * 27 * OC + oc;
#pragma unroll
        for (int hxr = 0; hxr < 4; hxr++) {
            const int hx = 2 * ph - 1 + hxr;
            const bool hok = SAFE || ((unsigned)hx < (unsigned)H);
            ull xq[3][7];
#pragma unroll
            for (int c = 0; c < 3; c++) {
                float xr[8];
#pragma unroll
                for (int i = 0; i < 8; i++) {
                    bool ok = hok;
                    if (i == 0) ok = ok && !dlo;
                    if (i == 7) ok = ok && !dhi;
                    xr[i] = ok ? xb[(((dsl + i) * H + hx) * 3 + c) * IC] : 0.f;
                }
#pragma unroll
                for (int i = 0; i < 7; i++) xq[c][i] = pk2(xr[i], xr[i + 1]);
            }
#pragma unroll
            for (int ch = 0; ch < 2; ch++) {
                const int kh = hxr - ch;
                if (kh < 0 || kh > 2) continue;
#pragma unroll
                for (int kd = 0; kd < 3; kd++) {
                    const ull* wp = wb + (kd * 9 + kh * 3) * OC;
                    const ull W0 = wp[0];
                    const ull W1 = wp[OC];
                    const ull W2 = wp[2 * OC];
#pragma unroll
                    for (int p = 0; p < 3; p++) {
                        const int xi = 2 * p + kd;
                        fma2(acc[p][ch][0], W1, xq[0][xi]);
                        fma2(acc[p][ch][0], W2, xq[1][xi]);
                        fma2(acc[p][ch][1], W0, xq[0][xi]);
                        fma2(acc[p][ch][1], W1, xq[1][xi]);
                        fma2(acc[p][ch][1], W2, xq[2][xi]);
                        fma2(acc[p][ch][2], W0, xq[1][xi]);
                        fma2(acc[p][ch][2], W1, xq[2][xi]);
                    }
                }
            }
        }
    }
}

template <int IC, int OC, int D, int H, int WCH, int NDH>
__global__ __launch_bounds__(576, 1) void conv_k(
    const float* __restrict__ x, const ull* __restrict__ wT,
    const float* __restrict__ bias, float* __restrict__ out)
{
    constexpr int H2 = H / 2;
    constexpr int D2 = D / 2;
    constexpr int DSLAB = 6 * NDH + 1;
    constexpr int SLAB = DSLAB * H * 3 * IC;
    constexpr int WSZ = WCH * 27 * OC;
    extern __shared__ float sm_[];
    float* xs = sm_;
    ull* ws = (ull*)(sm_ + SLAB);

    const int b = blockIdx.x;
    const int half = blockIdx.y;
    const int dbase = half * (6 * NDH - 1);
    const int tid = threadIdx.x;
    const int oc = tid % OC;
    const int ph = tid / OC;

    {   // NCDHW -> transposed slab
        const float* xb = x + (size_t)b * IC * D * H * 3;
        for (int i = tid; i < SLAB; i += 576) {
            const int ic = i / (DSLAB * H * 3), s = i - ic * (DSLAB * H * 3);
            xs[s * IC + ic] = xb[ic * D * H * 3 + dbase * H * 3 + s];
        }
    }
    {
        const ulonglong2* wsrc = (const ulonglong2*)wT;
        ulonglong2* wdst = (ulonglong2*)ws;
        for (int i = tid; i < WSZ / 2; i += 576) wdst[i] = wsrc[i];
    }
    __syncthreads();

    const bool hsafe = (ph > 0) && (ph < H2 - 1);
    const float bv = __ldg(&bias[oc]);

#pragma unroll 1
    for (int pdb = 0; pdb < NDH; pdb++) {
        ull acc[3][2][3];
#pragma unroll
        for (int p = 0; p < 3; p++)
#pragma unroll
            for (int c = 0; c < 2; c++)
#pragma unroll
                for (int w = 0; w < 3; w++) acc[p][c][w] = 0ull;

        const bool dlo = (half == 0) && (pdb == 0);
        const bool dhi = (half == 1) && (pdb == NDH - 1);
        const int dsl = 6 * pdb - 1 + half;

        if (hsafe)
            conv_acc<IC, OC, DSLAB, H, WCH, true>(xs, ws, oc, 0, dsl, ph, dlo, dhi, acc);
        else
            conv_acc<IC, OC, DSLAB, H, WCH, false>(xs, ws, oc, 0, dsl, ph, dlo, dhi, acc);

#pragma unroll
        for (int p = 0; p < 3; p++) {
            const int pd = (half * NDH + pdb) * 3 + p;
#pragma unroll
            for (int pw = 0; pw < 3; pw++) {
                const float2 u0 = upk(acc[p][0][pw]);
                const float2 u1 = upk(acc[p][1][pw]);
                float m = fmaxf(fmaxf(u0.x, u0.y), fmaxf(u1.x, u1.y)) + bv;
                out[((((size_t)b * D2 + pd) * H2 + ph) * 3 + pw) * OC + oc] = fmaxf(m, 0.f);
            }
        }
    }
}

// ---------------------------------------------------------------------------
// conv2/conv3: tf32 mma.sync implicit GEMM, v3 (big tiles, smem frags,
// conflict-free strided slab STR=IC+4, 512 threads, 1 block/SM).
//   block = (batch, d-group of DR, n-chunk of NT*16 channels)
//   slab: [Dp][Hp][Wp] rows of STR words, tf32-converted, zero-padded.
// ---------------------------------------------------------------------------
template <int IC, int D, int H, int DR, int NT, int N8TOT, bool POOLIN>
__global__ __launch_bounds__(512) void conv_mma3(
    const float* __restrict__ x, const float* __restrict__ pbias,
    const float2* __restrict__ fragG, float* __restrict__ outRaw)
{
    constexpr int KC = IC / 8;
    constexpr int STR = IC + 4;
    constexpr int Dp = DR + 2, Hp = H + 2, Wp = 5;
    constexpr int SLABW = Dp * Hp * Wp * STR;
    constexpr int M = DR * H * 3;
    constexpr int MT = (M + 15) / 16;
    constexpr int N8B = 2 * NT;
    constexpr int FRAG = 27 * KC * N8B * 32;
    constexpr int OCTOT = N8TOT * 8;
    constexpr int IC4 = IC / 4;

    extern __shared__ __align__(16) char smraw[];
    float* xs = (float*)smraw;                   // SLABW words
    float2* bfs = (float2*)(smraw + SLABW * 4);  // FRAG float2

    const int b = blockIdx.x;
    const int d0 = blockIdx.y * DR;
    const int zn = blockIdx.z;
    const int tid = threadIdx.x;

    // ---- zero slab ----
    for (int i = tid; i < SLABW; i += 512) xs[i] = 0.f;
    // ---- stage B fragments ----
    for (int i = tid; i < FRAG; i += 512) {
        const int lane = i & 31; const int r = i >> 5;
        const int n8l = r % N8B; const int tk = r / N8B;
        bfs[i] = __ldg(&fragG[((size_t)tk * N8TOT + zn * N8B + n8l) * 32 + lane]);
    }
    __syncthreads();

    // ---- fill valid region (tf32-converted, float4 granularity) ----
    for (int i = tid; i < Dp * H * 3 * IC4; i += 512) {
        const int ic4 = i % IC4; int r = i / IC4;
        const int w = r % 3; r /= 3;
        const int h = r % H; const int dp = r / H;
        const int d = d0 - 1 + dp;
        if ((unsigned)d >= (unsigned)D) continue;
        float4 v;
        if (POOLIN) {
            const float* p = x + ((((size_t)b * 2 * D + 2 * d) * 2 * H + 2 * h) * 3 + w) * IC + ic4 * 4;
            const int sd = 2 * H * 3 * IC, sh = 3 * IC;
            const float4 v0 = *(const float4*)p;
            const float4 v1 = *(const float4*)(p + sd);
            const float4 v2 = *(const float4*)(p + sh);
            const float4 v3 = *(const float4*)(p + sd + sh);
            const float4 bb = __ldg((const float4*)&pbias[ic4 * 4]);
            v.x = fmaxf(fmaxf(fmaxf(v0.x, v1.x), fmaxf(v2.x, v3.x)) + bb.x, 0.f);
            v.y = fmaxf(fmaxf(fmaxf(v0.y, v1.y), fmaxf(v2.y, v3.y)) + bb.y, 0.f);
            v.z = fmaxf(fmaxf(fmaxf(v0.z, v1.z), fmaxf(v2.z, v3.z)) + bb.z, 0.f);
            v.w = fmaxf(fmaxf(fmaxf(v0.w, v1.w), fmaxf(v2.w, v3.w)) + bb.w, 0.f);
        } else {
            v = *(const float4*)(x + ((((size_t)b * D + d) * H + h) * 3 + w) * IC + ic4 * 4);
        }
        float4 o;
        o.x = __uint_as_float(ctf(v.x));
        o.y = __uint_as_float(ctf(v.y));
        o.z = __uint_as_float(ctf(v.z));
        o.w = __uint_as_float(ctf(v.w));
        *(float4*)&xs[((dp * Hp + (h + 1)) * Wp + (w + 1)) * STR + ic4 * 4] = o;
    }
    __syncthreads();

    const int warp = tid >> 5, lane = tid & 31;
    const int gid = lane >> 2, tig = lane & 3;
    const uint32_t* xsu = (const uint32_t*)xs;

#pragma unroll 1
    for (int item = warp; item < MT * NT; item += 16) {
        const int nt = item % NT, mt = item / NT;
        const int r0 = mt * 16 + gid, r1 = r0 + 8;
        const bool v0 = r0 < M, v1 = r1 < M;
        const int q0 = v0 ? r0 : M - 1, q1 = v1 ? r1 : M - 1;
        const int dl0 = q0 / (H * 3), t0r = q0 - dl0 * H * 3;
        const int h0 = t0r / 3, w0 = t0r - h0 * 3;
        const int dl1 = q1 / (H * 3), t1r = q1 - dl1 * H * 3;
        const int h1 = t1r / 3, w1 = t1r - h1 * 3;
        const int base0 = ((dl0 * Hp + h0) * Wp + w0) * STR + tig;
        const int base1 = ((dl1 * Hp + h1) * Wp + w1) * STR + tig;
        const float2* bfi = bfs + (nt * 2) * 32 + lane;

        float acc0[4] = {0.f, 0.f, 0.f, 0.f};
        float acc1[4] = {0.f, 0.f, 0.f, 0.f};

#pragma unroll 9
        for (int t = 0; t < 27; t++) {
            const int kd = t / 9, kr = t - kd * 9, kh = kr / 3, kw = kr - kh * 3;
            const int toff = ((kd * Hp + kh) * Wp + kw) * STR;
#pragma unroll
            for (int kc = 0; kc < KC; kc++) {
                const int ko = toff + kc * 8;
                const uint32_t a0 = xsu[base0 + ko];
                const uint32_t a1 = xsu[base1 + ko];
                const uint32_t a2 = xsu[base0 + ko + 4];
                const uint32_t a3 = xsu[base1 + ko + 4];
                const float2 bA = bfi[(t * KC + kc) * N8B * 32];
                const float2 bB = bfi[(t * KC + kc) * N8B * 32 + 32];
                mma8(acc0, a0, a1, a2, a3, __float_as_uint(bA.x), __float_as_uint(bA.y));
                mma8(acc1, a0, a1, a2, a3, __float_as_uint(bB.x), __float_as_uint(bB.y));
            }
        }

        const int nb = (zn * N8B + nt * 2) * 8 + tig * 2;
        if (v0) {
            float* o = outRaw + ((((size_t)b * D + (d0 + dl0)) * H + h0) * 3 + w0) * OCTOT + nb;
            *(float2*)o = make_float2(acc0[0], acc0[1]);
            *(float2*)(o + 8) = make_float2(acc1[0], acc1[1]);
        }
        if (v1) {
            float* o = outRaw + ((((size_t)b * D + (d0 + dl1)) * H + h1) * 3 + w1) * OCTOT + nb;
            *(float2*)o = make_float2(acc0[2], acc0[3]);
            *(float2*)(o + 8) = make_float2(acc1[2], acc1[3]);
        }
    }
}

// pool conv3 raw -> g_buf3 (bias+relu)
__global__ __launch_bounds__(256) void pool3_kernel(const float* __restrict__ b3)
{
    const int i = blockIdx.x * 256 + threadIdx.x;
    if (i >= B_SZ * 3 * 9 * 3 * 64) return;
    const int c = i & 63; int r = i >> 6;
    const int w = r % 3; r /= 3;
    const int ph = r % 9; r /= 9;
    const int pd = r % 3; const int b = r / 3;
    const float* p = g_p3 + ((((size_t)b * 6 + 2 * pd) * 18 + 2 * ph) * 3 + w) * 64 + c;
    const int sd = 18 * 3 * 64, sh = 3 * 64;
    const float m = fmaxf(fmaxf(p[0], p[sd]), fmaxf(p[sh], p[sd + sh]));
    g_buf3[i] = fmaxf(m + __ldg(&b3[c]), 0.f);
}

// ---------------------------------------------------------------------------
// prep: mean over 81 positions -> h, ih_const, h2
// ---------------------------------------------------------------------------
__global__ __launch_bounds__(256) void prep_kernel(
    const float* __restrict__ b_init_h, const float* __restrict__ bih1,
    const float* __restrict__ bhh1, const float* __restrict__ b_init_h2)
{
    __shared__ __align__(16) float ms[64];
    __shared__ __align__(16) float hsh[256];
    const int b = blockIdx.x, j = threadIdx.x;
    if (j < 64) {
        float s = 0.f;
        const float* p = g_buf3 + (size_t)b * FLATN + j;
        for (int q = 0; q < 81; q++) s += p[q * 64];
        ms[j] = s * (1.f / 81.f);
    }
    __syncthreads();
    ull aA = 0ull, aB = 0ull;
#pragma unroll
    for (int k4 = 0; k4 < 16; k4++) {
        const ulonglong2 wa = g_wAq[k4 * 256 + j];
        const ulonglong2 wb = g_wBq[k4 * 256 + j];
        const ulonglong2 mv = *(const ulonglong2*)&ms[k4 * 4];
        fma2(aA, wa.x, mv.x); fma2(aA, wa.y, mv.y);
        fma2(aB, wb.x, mv.x); fma2(aB, wb.y, mv.y);
    }
    const float2 uA = upk(aA);
    const float2 uB = upk(aB);
    const float h = uA.x + uA.y + b_init_h[j];
    g_h[(size_t)b * HID + j] = h;
    g_ih[(size_t)b * HID + j] = uB.x + uB.y + bih1[j] + bhh1[j];
    hsh[j] = h;
    __syncthreads();
    ull aC = 0ull;
#pragma unroll 8
    for (int k4 = 0; k4 < 64; k4++) {
        const ulonglong2 wc = g_wCq[k4 * 256 + j];
        const ulonglong2 hv = *(const ulonglong2*)&hsh[k4 * 4];
        fma2(aC, wc.x, hv.x); fma2(aC, wc.y, hv.y);
    }
    const float2 uC = upk(aC);
    g_h2[(size_t)b * HID + j] = uC.x + uC.y + b_init_h2[j];
}

// ---------------------------------------------------------------------------
// 512 threads/block. Blocks 0..63: RNN, 8 rows (two 4-row groups);
// blocks 64..127: lin1, 8 rows.
// ---------------------------------------------------------------------------
__global__ __launch_bounds__(512) void rnn_lin1_kernel(
    const float* __restrict__ bih2, const float* __restrict__ bhh2,
    const float* __restrict__ w_fc, const float* __restrict__ b_fc,
    const float* __restrict__ b_lin1, float* __restrict__ pred_out)
{
    __shared__ __align__(16) float sm[6400];
    const int tid = threadIdx.x;
    const int rg = tid >> 8;
    const int j = tid & 255;

    if (blockIdx.x < 64) {
        float* h_s  = sm;
        float* h2_s = sm + 2048;
        float* ih_s = sm + 4096;
        float* red  = sm + 6144;
        const int r0 = blockIdx.x * 8;
        const int warp = tid >> 5, lane = tid & 31;

#pragma unroll
        for (int r = 0; r < 4; r++) {
            const int row = rg * 4 + r;
            h_s[row * 256 + j]  = g_h[(size_t)(r0 + row) * HID + j];
            h2_s[row * 256 + j] = g_h2[(size_t)(r0 + row) * HID + j];
            ih_s[row * 256 + j] = g_ih[(size_t)(r0 + row) * HID + j];
        }
        const float bias2 = bih2[j] + bhh2[j];
        const float wf = w_fc[j];
        const float bfc = b_fc[0];
        __syncthreads();

        const ulonglong2* W1 = g_wt;
        const ulonglong2* W2 = g_wt + 16384;
        const ulonglong2* W3 = g_wt + 32768;

        for (int t = 0; t < TLEN; t++) {
            ull a1[4];
#pragma unroll
            for (int r = 0; r < 4; r++) a1[r] = 0ull;
#pragma unroll 4
            for (int k4 = 0; k4 < 64; k4++) {
                const ulonglong2 wv = W1[k4 * 256 + j];
#pragma unroll
                for (int r = 0; r < 4; r++) {
                    const ulonglong2 hv = *(const ulonglong2*)&h_s[(rg * 4 + r) * 256 + k4 * 4];
                    fma2(a1[r], wv.x, hv.x);
                    fma2(a1[r], wv.y, hv.y);
                }
            }
            float hn[4];
#pragma unroll
            for (int r = 0; r < 4; r++) {
                const float2 u = upk(a1[r]);
                hn[r] = tanhf(ih_s[(rg * 4 + r) * 256 + j] + u.x + u.y);
            }
            __syncthreads();
#pragma unroll
            for (int r = 0; r < 4; r++) h_s[(rg * 4 + r) * 256 + j] = hn[r];
            __syncthreads();

            ull a2[4];
#pragma unroll
            for (int r = 0; r < 4; r++) a2[r] = 0ull;
#pragma unroll 2
            for (int k4 = 0; k4 < 64; k4++) {
                const ulonglong2 wv2 = W2[k4 * 256 + j];
                const ulonglong2 wv3 = W3[k4 * 256 + j];
#pragma unroll
                for (int r = 0; r < 4; r++) {
                    const ulonglong2 hv = *(const ulonglong2*)&h_s[(rg * 4 + r) * 256 + k4 * 4];
                    const ulonglong2 gv = *(const ulonglong2*)&h2_s[(rg * 4 + r) * 256 + k4 * 4];
                    fma2(a2[r], wv2.x, hv.x);
                    fma2(a2[r], wv2.y, hv.y);
                    fma2(a2[r], wv3.x, gv.x);
                    fma2(a2[r], wv3.y, gv.y);
                }
            }
            float h2n[4];
#pragma unroll
            for (int r = 0; r < 4; r++) {
                const float2 u = upk(a2[r]);
                h2n[r] = tanhf(bias2 + u.x + u.y);
            }
            __syncthreads();
#pragma unroll
            for (int r = 0; r < 4; r++) h2_s[(rg * 4 + r) * 256 + j] = h2n[r];

#pragma unroll
            for (int r = 0; r < 4; r++) {
                float v = h2n[r] * wf;
                v += __shfl_down_sync(0xffffffffu, v, 16);
                v += __shfl_down_sync(0xffffffffu, v, 8);
                v += __shfl_down_sync(0xffffffffu, v, 4);
                v += __shfl_down_sync(0xffffffffu, v, 2);
                v += __shfl_down_sync(0xffffffffu, v, 1);
                if (lane == 0) red[warp * 4 + r] = v;
            }
            __syncthreads();
            if (tid < 8) {
                const int g = tid >> 2;
                float s = bfc;
#pragma unroll
                for (int w = 0; w < 8; w++) s += red[((g << 3) + w) * 4 + (tid & 3)];
                pred_out[(size_t)(r0 + tid) * TLEN + t] = s;
            }
            __syncthreads();
        }
    } else {
        float* fs = sm;    // [8][648]
        const int r0 = (blockIdx.x - 64) * 8;
        ull acc[4];
#pragma unroll
        for (int r = 0; r < 4; r++) acc[r] = 0ull;

        for (int kb = 0; kb < FLATN; kb += 648) {
            __syncthreads();
            for (int i = tid; i < 8 * 648; i += 512) {
                const int r = i / 648, k = i - r * 648;
                fs[i] = g_buf3[(size_t)(r0 + r) * FLATN + kb + k];
            }
            __syncthreads();
            const int k4b = kb / 4;
#pragma unroll 2
            for (int k4 = 0; k4 < 162; k4++) {
                const ulonglong2 wv = g_wl1t[(k4b + k4) * 256 + j];
#pragma unroll
                for (int r = 0; r < 4; r++) {
                    const ulonglong2 hv = *(const ulonglong2*)&fs[(rg * 4 + r) * 648 + k4 * 4];
                    fma2(acc[r], wv.x, hv.x);
                    fma2(acc[r], wv.y, hv.y);
                }
            }
        }
        const float bb = b_lin1[j];
#pragma unroll
        for (int r = 0; r < 4; r++) {
            const float2 u = upk(acc[r]);
            g_t1[(size_t)(r0 + rg * 4 + r) * HID + j] = tanhf(u.x + u.y + bb);
        }
    }
}

__global__ __launch_bounds__(384) void lin2_kernel(
    const float* __restrict__ w_lin2, const float* __restrict__ b_lin2,
    float* __restrict__ outc)
{
    const int b = blockIdx.x;
    const int m = threadIdx.x >> 5;
    const int lane = threadIdx.x & 31;
    const float* tr = &g_t1[(size_t)b * HID];
    const float* wr = &w_lin2[(size_t)m * HID];
    float s = 0.f;
    for (int k = lane; k < HID; k += 32) s += tr[k] * wr[k];
    s += __shfl_down_sync(0xffffffffu, s, 16);
    s += __shfl_down_sync(0xffffffffu, s, 8);
    s += __shfl_down_sync(0xffffffffu, s, 4);
    s += __shfl_down_sync(0xffffffffu, s, 2);
    s += __shfl_down_sync(0xffffffffu, s, 1);
    if (lane == 0) outc[b * 12 + m] = s + b_lin2[m];
}

// ---------------------------------------------------------------------------

extern "C" void kernel_launch(void* const* d_in, const int* in_sizes, int n_in,
                              void* d_out, int out_size)
{
    const float* x        = (const float*)d_in[0];
    const float* w1       = (const float*)d_in[1];
    const float* b1       = (const float*)d_in[2];
    const float* w2       = (const float*)d_in[3];
    const float* b2       = (const float*)d_in[4];
    const float* w3       = (const float*)d_in[5];
    const float* b3       = (const float*)d_in[6];
    const float* wih1     = (const float*)d_in[7];
    const float* whh1     = (const float*)d_in[8];
    const float* bih1     = (const float*)d_in[9];
    const float* bhh1     = (const float*)d_in[10];
    const float* wih2     = (const float*)d_in[11];
    const float* whh2     = (const float*)d_in[12];
    const float* bih2     = (const float*)d_in[13];
    const float* bhh2     = (const float*)d_in[14];
    const float* w_init_h = (const float*)d_in[15];
    const float* b_init_h = (const float*)d_in[16];
    const float* w_init_h2= (const float*)d_in[17];
    const float* b_init_h2= (const float*)d_in[18];
    const float* w_fc     = (const float*)d_in[19];
    const float* b_fc     = (const float*)d_in[20];
    const float* w_lin1   = (const float*)d_in[21];
    const float* b_lin1   = (const float*)d_in[22];
    const float* w_lin2   = (const float*)d_in[23];
    const float* b_lin2   = (const float*)d_in[24];

    float* pred = (float*)d_out;
    float* outc = pred + B_SZ * TLEN;

    float *buf1, *p2, *p3;
    ull* wc1;
    float2 *f2, *f3;
    cudaGetSymbolAddress((void**)&buf1, g_buf1);
    cudaGetSymbolAddress((void**)&p2, g_p2);
    cudaGetSymbolAddress((void**)&p3, g_p3);
    cudaGetSymbolAddress((void**)&wc1, g_wc1);
    cudaGetSymbolAddress((void**)&f2, g_f2);
    cudaGetSymbolAddress((void**)&f3, g_f3);

    // order chosen so profiled launch index 3 == conv2 MMA kernel
    pack_frag_kernel<<<135, 256>>>(w2, w3);                       // 0
    pack_convw_kernel<<<11, 256>>>(w1);                           // 1

    auto k1 = &conv_k<6, 16, 24, 72, 6, 2>;
    const int sm1 = 13 * 72 * 3 * 6 * 4 + 6 * 27 * 16 * 8;        // 88128
    cudaFuncSetAttribute(k1, cudaFuncAttributeMaxDynamicSharedMemorySize, sm1);
    k1<<<dim3(B_SZ, 2), 576, sm1>>>(x, wc1, b1, buf1);            // 2

    // conv2: IC=16, D=12, H=36, DR=6 (2 halves), NT=2 (all 32 oc), N8TOT=4
    auto k2 = &conv_mma3<16, 12, 36, 6, 2, 4, false>;
    const int sm2 = (8 * 38 * 5 * 20) * 4 + 27 * 2 * 4 * 32 * 8;  // 121600+55296=176896
    cudaFuncSetAttribute(k2, cudaFuncAttributeMaxDynamicSharedMemorySize, sm2);
    k2<<<dim3(B_SZ, 2, 1), 512, sm2>>>(buf1, b1, f2, p2);         // 3  <-- profiled

    // conv3: IC=32, D=6, H=18, DR=6 (no d-split), NT=2 (32 oc), N8TOT=8, 2 n-chunks
    auto k3 = &conv_mma3<32, 6, 18, 6, 2, 8, true>;
    const int sm3 = (8 * 20 * 5 * 36) * 4 + 27 * 4 * 4 * 32 * 8;  // 115200+110592=225792
    cudaFuncSetAttribute(k3, cudaFuncAttributeMaxDynamicSharedMemorySize, sm3);
    k3<<<dim3(B_SZ, 1, 2), 512, sm3>>>(p2, b2, f3, p3);           // 4

    pool3_kernel<<<(B_SZ * 3 * 9 * 3 * 64 + 255) / 256, 256>>>(b3);   // 5

    pack_weights_kernel<<<1584, 256>>>(whh1, wih2, whh2, w_init_h, wih1,
                                       w_init_h2, w_lin1);        // 6

    prep_kernel<<<B_SZ, 256>>>(b_init_h, bih1, bhh1, b_init_h2);  // 7
    rnn_lin1_kernel<<<128, 512>>>(bih2, bhh2, w_fc, b_fc, b_lin1, pred);
    lin2_kernel<<<B_SZ, 384>>>(w_lin2, b_lin2, outc);

    (void)in_sizes; (void)n_in; (void)out_size;
}

// round 14
// speedup vs baseline: 1.7590x; 1.1306x over previous
#include <cuda_runtime.h>
#include <cuda_bf16.h>
#include <cstdint>

#define B_SZ 512
#define HID 256
#define TLEN 23
#define FLATN 5184

typedef unsigned long long ull;

// ---------------- scratch ----------------
__device__ float g_p1[B_SZ * 24 * 72 * 3 * 16];     // conv1 RAW pre-pool NDHWC
__device__ float g_p2[B_SZ * 12 * 36 * 3 * 32];     // conv2 RAW pre-pool NDHWC
__device__ float g_p3[B_SZ * 6 * 18 * 3 * 64];      // conv3 RAW pre-pool NDHWC
__device__ float g_buf3[B_SZ * 3 * 9 * 3 * 64];     // conv3 pooled NDHWC == flat
__device__ float g_h[B_SZ * HID];
__device__ float g_h2[B_SZ * HID];
__device__ float g_ih[B_SZ * HID];
__device__ float g_t1[B_SZ * HID];

// tf32 weight fragments, B-fragment order: [((t*KC+kc)*N8TOT + n8)*32 + lane]
__device__ float2 g_f1[27 * 1 * 2 * 32];     // conv1: KC=1 (ic padded to 8), N8TOT=2
__device__ float2 g_f2[27 * 2 * 4 * 32];     // conv2: KC=2, N8TOT=4
__device__ float2 g_f3[27 * 4 * 8 * 32];     // conv3: KC=4, N8TOT=8

// matmul weights packed-transposed [k4][j]
__device__ ulonglong2 g_wt[3 * 64 * 256];
__device__ ulonglong2 g_wAq[16 * 256];
__device__ ulonglong2 g_wBq[16 * 256];
__device__ ulonglong2 g_wCq[64 * 256];
__device__ ulonglong2 g_wl1t[1296 * 256];

// ---------------- helpers ----------------
__device__ __forceinline__ void fma2(ull& acc, ull a, ull b) {
    asm("fma.rn.f32x2 %0, %1, %2, %0;" : "+l"(acc) : "l"(a), "l"(b));
}
__device__ __forceinline__ ull pk2(float lo, float hi) {
    ull r; asm("mov.b64 %0, {%1,%2};" : "=l"(r) : "f"(lo), "f"(hi)); return r;
}
__device__ __forceinline__ float2 upk(ull v) {
    float lo, hi; asm("mov.b64 {%0,%1}, %2;" : "=f"(lo), "=f"(hi) : "l"(v));
    return make_float2(lo, hi);
}
__device__ __forceinline__ uint32_t ctf(float v) {
    uint32_t r; asm("cvt.rna.tf32.f32 %0, %1;" : "=r"(r) : "f"(v)); return r;
}
__device__ __forceinline__ void mma8(float c[4], uint32_t a0, uint32_t a1,
                                     uint32_t a2, uint32_t a3,
                                     uint32_t b0, uint32_t b1) {
    asm("mma.sync.aligned.m16n8k8.row.col.f32.tf32.tf32.f32 "
        "{%0,%1,%2,%3}, {%4,%5,%6,%7}, {%8,%9}, {%0,%1,%2,%3};"
        : "+f"(c[0]), "+f"(c[1]), "+f"(c[2]), "+f"(c[3])
        : "r"(a0), "r"(a1), "r"(a2), "r"(a3), "r"(b0), "r"(b1));
}

// ---------------- weight packers ----------------
// conv2/conv3 tf32 B-frags: B[k][n], k = kc*8 + (lane&3) (+4), n = n8*8 + (lane>>2)
__global__ __launch_bounds__(256) void pack_frag_kernel(
    const float* __restrict__ w2, const float* __restrict__ w3)
{
    const int idx = blockIdx.x * 256 + threadIdx.x;
    if (idx < 6912) {                       // conv2
        const int lane = idx & 31; int r = idx >> 5;
        const int n8 = r % 4; r /= 4;
        const int kc = r % 2; const int t = r / 2;
        const int oc = n8 * 8 + (lane >> 2), c = lane & 3;
        const int ic0 = kc * 8 + c, ic1 = ic0 + 4;
        const float v0 = w2[((size_t)oc * 16 + ic0) * 27 + t];
        const float v1 = w2[((size_t)oc * 16 + ic1) * 27 + t];
        g_f2[idx] = make_float2(__uint_as_float(ctf(v0)), __uint_as_float(ctf(v1)));
    } else if (idx < 6912 + 27648) {        // conv3
        const int j = idx - 6912;
        const int lane = j & 31; int r = j >> 5;
        const int n8 = r % 8; r /= 8;
        const int kc = r % 4; const int t = r / 4;
        const int oc = n8 * 8 + (lane >> 2), c = lane & 3;
        const int ic0 = kc * 8 + c, ic1 = ic0 + 4;
        const float v0 = w3[((size_t)oc * 32 + ic0) * 27 + t];
        const float v1 = w3[((size_t)oc * 32 + ic1) * 27 + t];
        g_f3[j] = make_float2(__uint_as_float(ctf(v0)), __uint_as_float(ctf(v1)));
    }
}

// conv1 frags: IC padded 6->8 with zeros. KC=1, N8TOT=2.
__global__ __launch_bounds__(256) void pack_frag1_kernel(const float* __restrict__ w1)
{
    const int idx = blockIdx.x * 256 + threadIdx.x;
    if (idx >= 1728) return;
    const int lane = idx & 31; int r = idx >> 5;
    const int n8 = r % 2; const int t = r / 2;
    const int oc = n8 * 8 + (lane >> 2), c = lane & 3;
    const int ic0 = c, ic1 = c + 4;
    const float v0 = (ic0 < 6) ? w1[((size_t)oc * 6 + ic0) * 27 + t] : 0.f;
    const float v1 = (ic1 < 6) ? w1[((size_t)oc * 6 + ic1) * 27 + t] : 0.f;
    g_f1[idx] = make_float2(__uint_as_float(ctf(v0)), __uint_as_float(ctf(v1)));
}

__global__ __launch_bounds__(256) void pack_weights_kernel(
    const float* __restrict__ whh1, const float* __restrict__ wih2,
    const float* __restrict__ whh2, const float* __restrict__ w_init_h,
    const float* __restrict__ wih1, const float* __restrict__ w_init_h2,
    const float* __restrict__ w_lin1)
{
    const int idx = blockIdx.x * 256 + threadIdx.x;   // < 405504
    const float* src; ulonglong2* dst; int K; int local;
    if (idx < 49152)      { int m = idx / 16384; local = idx % 16384;
                            src = (m == 0) ? whh1 : ((m == 1) ? wih2 : whh2);
                            dst = g_wt + m * 16384; K = 256; }
    else if (idx < 53248) { local = idx - 49152; src = w_init_h;  dst = g_wAq;  K = 64; }
    else if (idx < 57344) { local = idx - 53248; src = wih1;      dst = g_wBq;  K = 64; }
    else if (idx < 73728) { local = idx - 57344; src = w_init_h2; dst = g_wCq;  K = 256; }
    else                  { local = idx - 73728; src = w_lin1;    dst = g_wl1t; K = 5184; }
    const int j = local % 256;
    const int k4 = local / 256;
    const float4 v = *(const float4*)&src[(size_t)j * K + k4 * 4];
    ulonglong2 o; o.x = pk2(v.x, v.y); o.y = pk2(v.z, v.w);
    dst[local] = o;
}

// ---------------------------------------------------------------------------
// conv_mma4: tf32 implicit-GEMM conv, fragment-reuse version.
//   item = m32 (two m16 tiles) x all N8B n8-slots  ->  2 wf/MMA.
//   slab: [Dp][Hp][Wp] rows of STR=ICP+4 words, tf32, zero-padded.
//   TRANSIN: x is NCDHW (conv1; ICR=6 padded to ICP=8).
//   POOLIN:  slab fill = maxpool(2,2,1)+bias+relu from previous RAW buffer.
// ---------------------------------------------------------------------------
template <int ICR, int ICP, int D, int H, int DR, int N8B, int N8TOT,
          bool POOLIN, bool TRANSIN>
__global__ __launch_bounds__(512) void conv_mma4(
    const float* __restrict__ x, const float* __restrict__ pbias,
    const float2* __restrict__ fragG, float* __restrict__ outRaw)
{
    constexpr int KC = ICP / 8;
    constexpr int STR = ICP + 4;
    constexpr int Dp = DR + 2, Hp = H + 2, Wp = 5;
    constexpr int SLABW = Dp * Hp * Wp * STR;
    constexpr int M = DR * H * 3;
    constexpr int MT2 = (M + 31) / 32;
    constexpr int FRAG = 27 * KC * N8B * 32;
    constexpr int OCTOT = N8TOT * 8;
    constexpr int IC4 = ICR / 4;   // used only when !TRANSIN (ICR mult of 4)

    extern __shared__ __align__(16) char smraw[];
    float* xs = (float*)smraw;                   // SLABW words (tf32 bits)
    float2* bfs = (float2*)(smraw + SLABW * 4);  // FRAG float2

    const int b = blockIdx.x;
    const int d0 = blockIdx.y * DR;
    const int zn = blockIdx.z;
    const int tid = threadIdx.x;

    for (int i = tid; i < SLABW; i += 512) xs[i] = 0.f;
    for (int i = tid; i < FRAG; i += 512) {
        const int lane = i & 31; const int r = i >> 5;
        const int n8l = r % N8B; const int tk = r / N8B;
        bfs[i] = __ldg(&fragG[((size_t)tk * N8TOT + zn * N8B + n8l) * 32 + lane]);
    }
    __syncthreads();

    if (TRANSIN) {
        // x NCDHW [ICR][D][H*3]; write word-scatter into slab
        for (int i = tid; i < ICR * Dp * H * 3; i += 512) {
            const int j = i % (H * 3); int r = i / (H * 3);
            const int dp = r % Dp; const int ic = r / Dp;
            const int d = d0 - 1 + dp;
            if ((unsigned)d >= (unsigned)D) continue;
            const float v = x[(((size_t)b * ICR + ic) * D + d) * (H * 3) + j];
            const int h = j / 3, w = j - h * 3;
            xs[((dp * Hp + (h + 1)) * Wp + (w + 1)) * STR + ic] =
                __uint_as_float(ctf(v));
        }
    } else {
        for (int i = tid; i < Dp * H * 3 * IC4; i += 512) {
            const int ic4 = i % IC4; int r = i / IC4;
            const int w = r % 3; r /= 3;
            const int h = r % H; const int dp = r / H;
            const int d = d0 - 1 + dp;
            if ((unsigned)d >= (unsigned)D) continue;
            float4 v;
            if (POOLIN) {
                const float* p = x + ((((size_t)b * 2 * D + 2 * d) * 2 * H + 2 * h) * 3 + w) * ICR + ic4 * 4;
                const int sd = 2 * H * 3 * ICR, sh = 3 * ICR;
                const float4 v0 = *(const float4*)p;
                const float4 v1 = *(const float4*)(p + sd);
                const float4 v2 = *(const float4*)(p + sh);
                const float4 v3 = *(const float4*)(p + sd + sh);
                const float4 bb = __ldg((const float4*)&pbias[ic4 * 4]);
                v.x = fmaxf(fmaxf(fmaxf(v0.x, v1.x), fmaxf(v2.x, v3.x)) + bb.x, 0.f);
                v.y = fmaxf(fmaxf(fmaxf(v0.y, v1.y), fmaxf(v2.y, v3.y)) + bb.y, 0.f);
                v.z = fmaxf(fmaxf(fmaxf(v0.z, v1.z), fmaxf(v2.z, v3.z)) + bb.z, 0.f);
                v.w = fmaxf(fmaxf(fmaxf(v0.w, v1.w), fmaxf(v2.w, v3.w)) + bb.w, 0.f);
            } else {
                v = *(const float4*)(x + ((((size_t)b * D + d) * H + h) * 3 + w) * ICR + ic4 * 4);
            }
            float4 o;
            o.x = __uint_as_float(ctf(v.x));
            o.y = __uint_as_float(ctf(v.y));
            o.z = __uint_as_float(ctf(v.z));
            o.w = __uint_as_float(ctf(v.w));
            *(float4*)&xs[((dp * Hp + (h + 1)) * Wp + (w + 1)) * STR + ic4 * 4] = o;
        }
    }
    __syncthreads();

    const int warp = tid >> 5, lane = tid & 31;
    const int gid = lane >> 2, tig = lane & 3;
    const uint32_t* xsu = (const uint32_t*)xs;

#pragma unroll 1
    for (int item = warp; item < MT2; item += 16) {
        // 4 m8-row groups: s=0,1 -> m16 tile 0; s=2,3 -> tile 1
        int bases[4], qrow[4]; bool vv[4];
#pragma unroll
        for (int s = 0; s < 4; s++) {
            const int r = item * 32 + s * 8 + gid;
            vv[s] = r < M;
            const int q = vv[s] ? r : M - 1;
            qrow[s] = q;
            const int dl = q / (H * 3), tr = q - dl * (H * 3);
            const int h = tr / 3, w = tr - h * 3;
            bases[s] = ((dl * Hp + h) * Wp + w) * STR + tig;
        }

        float acc[2][N8B][4];
#pragma unroll
        for (int ti = 0; ti < 2; ti++)
#pragma unroll
            for (int n8 = 0; n8 < N8B; n8++)
#pragma unroll
                for (int c = 0; c < 4; c++) acc[ti][n8][c] = 0.f;

#pragma unroll 9
        for (int t = 0; t < 27; t++) {
            const int kd = t / 9, kr = t - kd * 9, kh = kr / 3, kw = kr - kh * 3;
            const int toff = ((kd * Hp + kh) * Wp + kw) * STR;
#pragma unroll
            for (int kc = 0; kc < KC; kc++) {
                const int ko = toff + kc * 8;
                uint32_t A[4][2];
#pragma unroll
                for (int s = 0; s < 4; s++) {
                    A[s][0] = xsu[bases[s] + ko];
                    A[s][1] = xsu[bases[s] + ko + 4];
                }
                const float2* bp = bfs + (t * KC + kc) * N8B * 32 + lane;
#pragma unroll
                for (int n8 = 0; n8 < N8B; n8++) {
                    const float2 bb = bp[n8 * 32];
                    mma8(acc[0][n8], A[0][0], A[1][0], A[0][1], A[1][1],
                         __float_as_uint(bb.x), __float_as_uint(bb.y));
                    mma8(acc[1][n8], A[2][0], A[3][0], A[2][1], A[3][1],
                         __float_as_uint(bb.x), __float_as_uint(bb.y));
                }
            }
        }

        // store: group s holds c{0,1} (s even) / c{2,3} (s odd) of tile s/2
#pragma unroll
        for (int s = 0; s < 4; s++) {
            if (!vv[s]) continue;
            const int q = qrow[s];
            const int dl = q / (H * 3), tr = q - dl * (H * 3);
            const int h = tr / 3, w = tr - h * 3;
            float* o = outRaw + ((((size_t)b * D + (d0 + dl)) * H + h) * 3 + w) * OCTOT
                     + (zn * N8B) * 8 + tig * 2;
            const int ti = s >> 1, off = (s & 1) * 2;
#pragma unroll
            for (int n8 = 0; n8 < N8B; n8++)
                *(float2*)(o + n8 * 8) =
                    make_float2(acc[ti][n8][off], acc[ti][n8][off + 1]);
        }
    }
}

// pool conv3 raw -> g_buf3 (bias+relu)
__global__ __launch_bounds__(256) void pool3_kernel(const float* __restrict__ b3)
{
    const int i = blockIdx.x * 256 + threadIdx.x;
    if (i >= B_SZ * 3 * 9 * 3 * 64) return;
    const int c = i & 63; int r = i >> 6;
    const int w = r % 3; r /= 3;
    const int ph = r % 9; r /= 9;
    const int pd = r % 3; const int b = r / 3;
    const float* p = g_p3 + ((((size_t)b * 6 + 2 * pd) * 18 + 2 * ph) * 3 + w) * 64 + c;
    const int sd = 18 * 3 * 64, sh = 3 * 64;
    const float m = fmaxf(fmaxf(p[0], p[sd]), fmaxf(p[sh], p[sd + sh]));
    g_buf3[i] = fmaxf(m + __ldg(&b3[c]), 0.f);
}

// ---------------------------------------------------------------------------
// prep: mean over 81 positions -> h, ih_const, h2
// ---------------------------------------------------------------------------
__global__ __launch_bounds__(256) void prep_kernel(
    const float* __restrict__ b_init_h, const float* __restrict__ bih1,
    const float* __restrict__ bhh1, const float* __restrict__ b_init_h2)
{
    __shared__ __align__(16) float ms[64];
    __shared__ __align__(16) float hsh[256];
    const int b = blockIdx.x, j = threadIdx.x;
    if (j < 64) {
        float s = 0.f;
        const float* p = g_buf3 + (size_t)b * FLATN + j;
        for (int q = 0; q < 81; q++) s += p[q * 64];
        ms[j] = s * (1.f / 81.f);
    }
    __syncthreads();
    ull aA = 0ull, aB = 0ull;
#pragma unroll
    for (int k4 = 0; k4 < 16; k4++) {
        const ulonglong2 wa = g_wAq[k4 * 256 + j];
        const ulonglong2 wb = g_wBq[k4 * 256 + j];
        const ulonglong2 mv = *(const ulonglong2*)&ms[k4 * 4];
        fma2(aA, wa.x, mv.x); fma2(aA, wa.y, mv.y);
        fma2(aB, wb.x, mv.x); fma2(aB, wb.y, mv.y);
    }
    const float2 uA = upk(aA);
    const float2 uB = upk(aB);
    const float h = uA.x + uA.y + b_init_h[j];
    g_h[(size_t)b * HID + j] = h;
    g_ih[(size_t)b * HID + j] = uB.x + uB.y + bih1[j] + bhh1[j];
    hsh[j] = h;
    __syncthreads();
    ull aC = 0ull;
#pragma unroll 8
    for (int k4 = 0; k4 < 64; k4++) {
        const ulonglong2 wc = g_wCq[k4 * 256 + j];
        const ulonglong2 hv = *(const ulonglong2*)&hsh[k4 * 4];
        fma2(aC, wc.x, hv.x); fma2(aC, wc.y, hv.y);
    }
    const float2 uC = upk(aC);
    g_h2[(size_t)b * HID + j] = uC.x + uC.y + b_init_h2[j];
}

// ---------------------------------------------------------------------------
// 512 threads/block. Blocks 0..63: RNN, 8 rows (two 4-row groups);
// blocks 64..127: lin1, 8 rows.
// ---------------------------------------------------------------------------
__global__ __launch_bounds__(512) void rnn_lin1_kernel(
    const float* __restrict__ bih2, const float* __restrict__ bhh2,
    const float* __restrict__ w_fc, const float* __restrict__ b_fc,
    const float* __restrict__ b_lin1, float* __restrict__ pred_out)
{
    __shared__ __align__(16) float sm[6400];
    const int tid = threadIdx.x;
    const int rg = tid >> 8;
    const int j = tid & 255;

    if (blockIdx.x < 64) {
        float* h_s  = sm;
        float* h2_s = sm + 2048;
        float* ih_s = sm + 4096;
        float* red  = sm + 6144;
        const int r0 = blockIdx.x * 8;
        const int warp = tid >> 5, lane = tid & 31;

#pragma unroll
        for (int r = 0; r < 4; r++) {
            const int row = rg * 4 + r;
            h_s[row * 256 + j]  = g_h[(size_t)(r0 + row) * HID + j];
            h2_s[row * 256 + j] = g_h2[(size_t)(r0 + row) * HID + j];
            ih_s[row * 256 + j] = g_ih[(size_t)(r0 + row) * HID + j];
        }
        const float bias2 = bih2[j] + bhh2[j];
        const float wf = w_fc[j];
        const float bfc = b_fc[0];
        __syncthreads();

        const ulonglong2* W1 = g_wt;
        const ulonglong2* W2 = g_wt + 16384;
        const ulonglong2* W3 = g_wt + 32768;

        for (int t = 0; t < TLEN; t++) {
            ull a1[4];
#pragma unroll
            for (int r = 0; r < 4; r++) a1[r] = 0ull;
#pragma unroll 4
            for (int k4 = 0; k4 < 64; k4++) {
                const ulonglong2 wv = W1[k4 * 256 + j];
#pragma unroll
                for (int r = 0; r < 4; r++) {
                    const ulonglong2 hv = *(const ulonglong2*)&h_s[(rg * 4 + r) * 256 + k4 * 4];
                    fma2(a1[r], wv.x, hv.x);
                    fma2(a1[r], wv.y, hv.y);
                }
            }
            float hn[4];
#pragma unroll
            for (int r = 0; r < 4; r++) {
                const float2 u = upk(a1[r]);
                hn[r] = tanhf(ih_s[(rg * 4 + r) * 256 + j] + u.x + u.y);
            }
            __syncthreads();
#pragma unroll
            for (int r = 0; r < 4; r++) h_s[(rg * 4 + r) * 256 + j] = hn[r];
            __syncthreads();

            ull a2[4];
#pragma unroll
            for (int r = 0; r < 4; r++) a2[r] = 0ull;
#pragma unroll 2
            for (int k4 = 0; k4 < 64; k4++) {
                const ulonglong2 wv2 = W2[k4 * 256 + j];
                const ulonglong2 wv3 = W3[k4 * 256 + j];
#pragma unroll
                for (int r = 0; r < 4; r++) {
                    const ulonglong2 hv = *(const ulonglong2*)&h_s[(rg * 4 + r) * 256 + k4 * 4];
                    const ulonglong2 gv = *(const ulonglong2*)&h2_s[(rg * 4 + r) * 256 + k4 * 4];
                    fma2(a2[r], wv2.x, hv.x);
                    fma2(a2[r], wv2.y, hv.y);
                    fma2(a2[r], wv3.x, gv.x);
                    fma2(a2[r], wv3.y, gv.y);
                }
            }
            float h2n[4];
#pragma unroll
            for (int r = 0; r < 4; r++) {
                const float2 u = upk(a2[r]);
                h2n[r] = tanhf(bias2 + u.x + u.y);
            }
            __syncthreads();
#pragma unroll
            for (int r = 0; r < 4; r++) h2_s[(rg * 4 + r) * 256 + j] = h2n[r];

#pragma unroll
            for (int r = 0; r < 4; r++) {
                float v = h2n[r] * wf;
                v += __shfl_down_sync(0xffffffffu, v, 16);
                v += __shfl_down_sync(0xffffffffu, v, 8);
                v += __shfl_down_sync(0xffffffffu, v, 4);
                v += __shfl_down_sync(0xffffffffu, v, 2);
                v += __shfl_down_sync(0xffffffffu, v, 1);
                if (lane == 0) red[warp * 4 + r] = v;
            }
            __syncthreads();
            if (tid < 8) {
                const int g = tid >> 2;
                float s = bfc;
#pragma unroll
                for (int w = 0; w < 8; w++) s += red[((g << 3) + w) * 4 + (tid & 3)];
                pred_out[(size_t)(r0 + tid) * TLEN + t] = s;
            }
            __syncthreads();
        }
    } else {
        float* fs = sm;    // [8][648]
        const int r0 = (blockIdx.x - 64) * 8;
        ull acc[4];
#pragma unroll
        for (int r = 0; r < 4; r++) acc[r] = 0ull;

        for (int kb = 0; kb < FLATN; kb += 648) {
            __syncthreads();
            for (int i = tid; i < 8 * 648; i += 512) {
                const int r = i / 648, k = i - r * 648;
                fs[i] = g_buf3[(size_t)(r0 + r) * FLATN + kb + k];
            }
            __syncthreads();
            const int k4b = kb / 4;
#pragma unroll 2
            for (int k4 = 0; k4 < 162; k4++) {
                const ulonglong2 wv = g_wl1t[(k4b + k4) * 256 + j];
#pragma unroll
                for (int r = 0; r < 4; r++) {
                    const ulonglong2 hv = *(const ulonglong2*)&fs[(rg * 4 + r) * 648 + k4 * 4];
                    fma2(acc[r], wv.x, hv.x);
                    fma2(acc[r], wv.y, hv.y);
                }
            }
        }
        const float bb = b_lin1[j];
#pragma unroll
        for (int r = 0; r < 4; r++) {
            const float2 u = upk(acc[r]);
            g_t1[(size_t)(r0 + rg * 4 + r) * HID + j] = tanhf(u.x + u.y + bb);
        }
    }
}

__global__ __launch_bounds__(384) void lin2_kernel(
    const float* __restrict__ w_lin2, const float* __restrict__ b_lin2,
    float* __restrict__ outc)
{
    const int b = blockIdx.x;
    const int m = threadIdx.x >> 5;
    const int lane = threadIdx.x & 31;
    const float* tr = &g_t1[(size_t)b * HID];
    const float* wr = &w_lin2[(size_t)m * HID];
    float s = 0.f;
    for (int k = lane; k < HID; k += 32) s += tr[k] * wr[k];
    s += __shfl_down_sync(0xffffffffu, s, 16);
    s += __shfl_down_sync(0xffffffffu, s, 8);
    s += __shfl_down_sync(0xffffffffu, s, 4);
    s += __shfl_down_sync(0xffffffffu, s, 2);
    s += __shfl_down_sync(0xffffffffu, s, 1);
    if (lane == 0) outc[b * 12 + m] = s + b_lin2[m];
}

// ---------------------------------------------------------------------------

extern "C" void kernel_launch(void* const* d_in, const int* in_sizes, int n_in,
                              void* d_out, int out_size)
{
    const float* x        = (const float*)d_in[0];
    const float* w1       = (const float*)d_in[1];
    const float* b1       = (const float*)d_in[2];
    const float* w2       = (const float*)d_in[3];
    const float* b2       = (const float*)d_in[4];
    const float* w3       = (const float*)d_in[5];
    const float* b3       = (const float*)d_in[6];
    const float* wih1     = (const float*)d_in[7];
    const float* whh1     = (const float*)d_in[8];
    const float* bih1     = (const float*)d_in[9];
    const float* bhh1     = (const float*)d_in[10];
    const float* wih2     = (const float*)d_in[11];
    const float* whh2     = (const float*)d_in[12];
    const float* bih2     = (const float*)d_in[13];
    const float* bhh2     = (const float*)d_in[14];
    const float* w_init_h = (const float*)d_in[15];
    const float* b_init_h = (const float*)d_in[16];
    const float* w_init_h2= (const float*)d_in[17];
    const float* b_init_h2= (const float*)d_in[18];
    const float* w_fc     = (const float*)d_in[19];
    const float* b_fc     = (const float*)d_in[20];
    const float* w_lin1   = (const float*)d_in[21];
    const float* b_lin1   = (const float*)d_in[22];
    const float* w_lin2   = (const float*)d_in[23];
    const float* b_lin2   = (const float*)d_in[24];

    float* pred = (float*)d_out;
    float* outc = pred + B_SZ * TLEN;

    float *p1, *p2, *p3;
    float2 *f1, *f2, *f3;
    cudaGetSymbolAddress((void**)&p1, g_p1);
    cudaGetSymbolAddress((void**)&p2, g_p2);
    cudaGetSymbolAddress((void**)&p3, g_p3);
    cudaGetSymbolAddress((void**)&f1, g_f1);
    cudaGetSymbolAddress((void**)&f2, g_f2);
    cudaGetSymbolAddress((void**)&f3, g_f3);

    pack_frag_kernel<<<135, 256>>>(w2, w3);                        // 0
    pack_weights_kernel<<<1584, 256>>>(whh1, wih2, whh2, w_init_h, wih1,
                                       w_init_h2, w_lin1);         // 1
    pack_frag1_kernel<<<7, 256>>>(w1);                             // 2

    // conv1: ICR=6->ICP=8, D=24, H=72, DR=6 (4 d-groups), N8B=2 (all 16 oc)
    auto k1 = &conv_mma4<6, 8, 24, 72, 6, 2, 2, false, true>;
    const int sm1 = (8 * 74 * 5 * 12) * 4 + 27 * 1 * 2 * 32 * 8;   // 142080+13824=155904
    cudaFuncSetAttribute(k1, cudaFuncAttributeMaxDynamicSharedMemorySize, sm1);
    k1<<<dim3(B_SZ, 4, 1), 512, sm1>>>(x, b1, f1, p1);             // 3  <-- profiled

    // conv2: IC=16, D=12, H=36, DR=6 (2 halves), N8B=4 (all 32 oc), POOLIN(b1)
    auto k2 = &conv_mma4<16, 16, 12, 36, 6, 4, 4, true, false>;
    const int sm2 = (8 * 38 * 5 * 20) * 4 + 27 * 2 * 4 * 32 * 8;   // 121600+55296=176896
    cudaFuncSetAttribute(k2, cudaFuncAttributeMaxDynamicSharedMemorySize, sm2);
    k2<<<dim3(B_SZ, 2, 1), 512, sm2>>>(p1, b1, f2, p2);            // 4

    // conv3: IC=32, D=6, H=18, DR=6, N8B=4, 2 n-chunks, POOLIN(b2)
    auto k3 = &conv_mma4<32, 32, 6, 18, 6, 4, 8, true, false>;
    const int sm3 = (8 * 20 * 5 * 36) * 4 + 27 * 4 * 4 * 32 * 8;   // 115200+110592=225792
    cudaFuncSetAttribute(k3, cudaFuncAttributeMaxDynamicSharedMemorySize, sm3);
    k3<<<dim3(B_SZ, 1, 2), 512, sm3>>>(p2, b2, f3, p3);            // 5

    pool3_kernel<<<(B_SZ * 3 * 9 * 3 * 64 + 255) / 256, 256>>>(b3);    // 6

    prep_kernel<<<B_SZ, 256>>>(b_init_h, bih1, bhh1, b_init_h2);   // 7
    rnn_lin1_kernel<<<128, 512>>>(bih2, bhh2, w_fc, b_fc, b_lin1, pred);
    lin2_kernel<<<B_SZ, 384>>>(w_lin2, b_lin2, outc);

    (void)in_sizes; (void)n_in; (void)out_size;
}